// round 11
// baseline (speedup 1.0000x reference)
#include <cuda_runtime.h>
#include <cuda_fp16.h>
#include <cstdint>
#include <math.h>

// Problem constants
#define NBATCH 2
#define HDIM   96
#define WDIM   96
#define CDIM   256
#define NHEADS 8
#define NPTS   25
#define DH     32
#define HIDDIM 1024
#define LQ     (HDIM*WDIM)      // 9216
#define NLTOK  (NBATCH*LQ)      // 18432
#define NQKV   896
#define OA_LD  600              // combined off(400)+attn(200) row stride

// ================= scratch (device globals, no allocation) =================
__device__ __align__(16) __half g_q  [NLTOK*CDIM];
__device__ __align__(16) __half g_at [NLTOK*CDIM];
__device__ __align__(16) __half g_q2 [NLTOK*CDIM];
__device__ __align__(16) __half g_h1 [NLTOK*HIDDIM];
__device__ __align__(16) __half g_val[NLTOK*CDIM];      // value [n,h,l,d], fp16
__device__ __align__(16) float  g_oa [NLTOK*OA_LD];
__device__ __align__(16) float  g_x1 [NLTOK*CDIM];
__device__ __align__(16) __half g_wq [NQKV*256];
__device__ __align__(16) __half g_wu [256*256];
__device__ __align__(16) __half g_w1 [1024*256];
__device__ __align__(16) __half g_w2 [256*1024];

// ================= low-level helpers ==================
__device__ __forceinline__ uint32_t smem_u32(const void* p) {
    uint32_t a;
    asm("{ .reg .u64 t; cvta.to.shared.u64 t, %1; cvt.u32.u64 %0, t; }" : "=r"(a) : "l"(p));
    return a;
}
__device__ __forceinline__ void cp16(uint32_t s, const void* g) {
    asm volatile("cp.async.cg.shared.global [%0], [%1], 16;" :: "r"(s), "l"(g));
}
#define CP_COMMIT() asm volatile("cp.async.commit_group;" ::: "memory")
#define CP_WAIT(n)  asm volatile("cp.async.wait_group %0;" :: "n"(n) : "memory")

__device__ __forceinline__ void ldm4(uint32_t* r, uint32_t addr) {
    asm volatile("ldmatrix.sync.aligned.m8n8.x4.shared.b16 {%0,%1,%2,%3}, [%4];"
                 : "=r"(r[0]), "=r"(r[1]), "=r"(r[2]), "=r"(r[3]) : "r"(addr));
}
__device__ __forceinline__ void mma_f16(float* d, const uint32_t* a, const uint32_t* b) {
    asm volatile("mma.sync.aligned.m16n8k16.row.col.f32.f16.f16.f32 "
                 "{%0,%1,%2,%3}, {%4,%5,%6,%7}, {%8,%9}, {%0,%1,%2,%3};"
                 : "+f"(d[0]), "+f"(d[1]), "+f"(d[2]), "+f"(d[3])
                 : "r"(a[0]), "r"(a[1]), "r"(a[2]), "r"(a[3]), "r"(b[0]), "r"(b[1]));
}

// ========== single mega weight-prep ========
__global__ void __launch_bounds__(256) wprep_all(const float* __restrict__ w_val,
                                                 const float* __restrict__ w_off,
                                                 const float* __restrict__ w_attn,
                                                 const float* __restrict__ w_out,
                                                 const float* __restrict__ w_fc1,
                                                 const float* __restrict__ w_fc2,
                                                 __half* __restrict__ wq,
                                                 __half* __restrict__ wu,
                                                 __half* __restrict__ w1,
                                                 __half* __restrict__ w2)
{
    int t = blockIdx.x;
    const float* src; __half* dst;
    int row0, K, N, Nallot, ktiles;
    if      (t < 64)  { src=w_val;  dst=wq; row0=0;   K=256;  N=256;  Nallot=256;  ktiles=8;  t -= 0; }
    else if (t < 168) { src=w_off;  dst=wq; row0=256; K=256;  N=400;  Nallot=400;  ktiles=8;  t -= 64; }
    else if (t < 232) { src=w_attn; dst=wq; row0=656; K=256;  N=200;  Nallot=240;  ktiles=8;  t -= 168; }
    else if (t < 296) { src=w_out;  dst=wu; row0=0;   K=256;  N=256;  Nallot=256;  ktiles=8;  t -= 232; }
    else if (t < 552) { src=w_fc1;  dst=w1; row0=0;   K=256;  N=1024; Nallot=1024; ktiles=8;  t -= 296; }
    else              { src=w_fc2;  dst=w2; row0=0;   K=1024; N=256;  Nallot=256;  ktiles=32; t -= 552; }
    int kt = t % ktiles, nt = t / ktiles;
    int k0 = kt * 32, n0 = nt * 32;

    __shared__ float s[32][33];
    int tx = threadIdx.x & 31, ty = threadIdx.x >> 5;
#pragma unroll
    for (int j = ty; j < 32; j += 8) {
        int n = n0 + tx;
        s[j][tx] = (n < N) ? src[(size_t)(k0 + j) * N + n] : 0.0f;
    }
    __syncthreads();
#pragma unroll
    for (int j = ty; j < 32; j += 8) {
        int n = n0 + j;
        if (n < Nallot)
            dst[(size_t)(row0 + n) * K + k0 + tx] = __float2half(s[tx][j]);
    }
}

// ================= LayerNorm ==========================
__global__ void __launch_bounds__(256) ln_kernel(const float* __restrict__ x,
                                                 const float* __restrict__ gam,
                                                 const float* __restrict__ bet,
                                                 __half* __restrict__ o)
{
    int warp = threadIdx.x >> 5, lane = threadIdx.x & 31;
    int token = blockIdx.x * 8 + warp;
    const float4* x4 = reinterpret_cast<const float4*>(x) + (size_t)token * 64;
    float4 v0 = x4[lane * 2];
    float4 v1 = x4[lane * 2 + 1];
    float s  = v0.x + v0.y + v0.z + v0.w + v1.x + v1.y + v1.z + v1.w;
    float sq = v0.x*v0.x + v0.y*v0.y + v0.z*v0.z + v0.w*v0.w
             + v1.x*v1.x + v1.y*v1.y + v1.z*v1.z + v1.w*v1.w;
#pragma unroll
    for (int of = 16; of > 0; of >>= 1) {
        s  += __shfl_xor_sync(0xffffffffu, s,  of);
        sq += __shfl_xor_sync(0xffffffffu, sq, of);
    }
    float mean = s * (1.0f / CDIM);
    float var  = sq * (1.0f / CDIM) - mean * mean;
    float rstd = rsqrtf(var + 1e-5f);
    const float4* g4 = reinterpret_cast<const float4*>(gam);
    const float4* b4 = reinterpret_cast<const float4*>(bet);
    float r[8];
    {
        float4 ga = g4[lane * 2],     ba = b4[lane * 2];
        float4 gb = g4[lane * 2 + 1], bb = b4[lane * 2 + 1];
        r[0] = (v0.x - mean) * rstd * ga.x + ba.x;
        r[1] = (v0.y - mean) * rstd * ga.y + ba.y;
        r[2] = (v0.z - mean) * rstd * ga.z + ba.z;
        r[3] = (v0.w - mean) * rstd * ga.w + ba.w;
        r[4] = (v1.x - mean) * rstd * gb.x + bb.x;
        r[5] = (v1.y - mean) * rstd * gb.y + bb.y;
        r[6] = (v1.z - mean) * rstd * gb.z + bb.z;
        r[7] = (v1.w - mean) * rstd * gb.w + bb.w;
    }
    size_t base = (size_t)token * CDIM + lane * 8;
#pragma unroll
    for (int i = 0; i < 8; i += 2)
        *reinterpret_cast<__half2*>(o + base + i) =
            __floats2half2_rn(r[i], r[i + 1]);
}

// ================= warp-MMA GEMM (3-stage cp.async) =========================
enum { EP_QKV = 0, EP_RESID = 2, EP_GELU = 3 };

__device__ __forceinline__ float gelu_exact(float v) {
    return 0.5f * v * (1.0f + erff(v * 0.70710678118654752f));
}

#define STAGE_BYTES 24576
#define B_OFF       16384
#define NSTAGE      3

template <int EPI>
__global__ void __launch_bounds__(256) mm_mma(const __half* __restrict__ A,
                                              const __half* __restrict__ B,
                                              const float* __restrict__ bias,
                                              float* __restrict__ Cout,
                                              const float* __restrict__ Res,
                                              __half* __restrict__ OutH,
                                              const float* __restrict__ b_off,
                                              const float* __restrict__ b_attn,
                                              float* __restrict__ OA,
                                              int K, int Nvalid, int ldc)
{
    extern __shared__ __align__(128) char smem[];
    const uint32_t sb = smem_u32(smem);
    const int tid = threadIdx.x;
    const int wid = tid >> 5, l = tid & 31;
    const int wm = wid & 3, wn = wid >> 2;
    const int m0 = blockIdx.y * 128, n0 = blockIdx.x * 64;

    float acc[2][4][4];
#pragma unroll
    for (int i = 0; i < 2; i++)
#pragma unroll
        for (int j = 0; j < 4; j++)
#pragma unroll
            for (int q = 0; q < 4; q++) acc[i][j][q] = 0.0f;

    const int KC = K >> 6;

    auto load_stage = [&](int kcidx, int slot) {
        int k0 = kcidx << 6;
        uint32_t st = sb + slot * STAGE_BYTES;
#pragma unroll
        for (int i = 0; i < 4; i++) {
            int id = tid + i * 256;
            int r = id >> 3, c = id & 7;
            cp16(st + r * 128 + ((c ^ (r & 7)) << 4),
                 A + (size_t)(m0 + r) * K + k0 + c * 8);
        }
#pragma unroll
        for (int i = 0; i < 2; i++) {
            int id = tid + i * 256;
            int r = id >> 3, c = id & 7;
            cp16(st + B_OFF + r * 128 + ((c ^ (r & 7)) << 4),
                 B + (size_t)(n0 + r) * K + k0 + c * 8);
        }
        CP_COMMIT();
    };

    // prologue: fill 2 stages (KC >= 2 always here)
    load_stage(0, 0);
    load_stage(1, 1);

    const int rowA = wm * 32 + (l & 15);
    const int cxA  = l >> 4;
    const int rowB = wn * 32 + (l & 7) + ((l >> 4) << 3);
    const int cxB  = (l >> 3) & 1;

    int cslot = 0, lslot = 2;
    for (int kc = 0; kc < KC; kc++) {
        if (kc + 2 < KC) {
            load_stage(kc + 2, lslot);
            if (++lslot == NSTAGE) lslot = 0;
            CP_WAIT(2);
        } else if (kc + 1 < KC) {
            CP_WAIT(1);
        } else {
            CP_WAIT(0);
        }
        __syncthreads();

        uint32_t ab = sb + cslot * STAGE_BYTES;
        uint32_t bb = ab + B_OFF;
        if (++cslot == NSTAGE) cslot = 0;
#pragma unroll
        for (int ks = 0; ks < 4; ks++) {
            uint32_t a[2][4], b[2][4];
#pragma unroll
            for (int mt = 0; mt < 2; mt++) {
                int row = rowA + mt * 16;
                ldm4(a[mt], ab + row * 128 + (((ks * 2 + cxA) ^ (row & 7)) << 4));
            }
#pragma unroll
            for (int ntp = 0; ntp < 2; ntp++) {
                int row = rowB + ntp * 16;
                ldm4(b[ntp], bb + row * 128 + (((ks * 2 + cxB) ^ (row & 7)) << 4));
            }
#pragma unroll
            for (int mt = 0; mt < 2; mt++)
#pragma unroll
                for (int nt = 0; nt < 4; nt++)
                    mma_f16(acc[mt][nt], a[mt], &b[nt >> 1][(nt & 1) * 2]);
        }
        __syncthreads();
    }

    // ---- epilogue ----
#pragma unroll
    for (int mt = 0; mt < 2; mt++) {
#pragma unroll
        for (int nt = 0; nt < 4; nt++) {
            int col = n0 + wn * 32 + nt * 8 + (l & 3) * 2;
            if (col >= Nvalid) continue;
#pragma unroll
            for (int half = 0; half < 2; half++) {
                int row = m0 + wm * 32 + mt * 16 + (l >> 2) + half * 8;
                float v0 = acc[mt][nt][half * 2];
                float v1 = acc[mt][nt][half * 2 + 1];
                if (EPI == EP_QKV) {
                    if (col < 256) {
                        float2 bv = *reinterpret_cast<const float2*>(bias + col);
                        v0 += bv.x; v1 += bv.y;
                        int n = row / LQ, li = row - n * LQ;
                        int h = col >> 5, d = col & 31;
                        *reinterpret_cast<__half2*>(OutH +
                            ((size_t)((n * NHEADS + h) * LQ + li)) * DH + d) =
                            __floats2half2_rn(v0, v1);
                    } else if (col < 656) {
                        float2 bv = *reinterpret_cast<const float2*>(b_off + (col - 256));
                        v0 += bv.x; v1 += bv.y;
                        *reinterpret_cast<float2*>(OA + (size_t)row * OA_LD + (col - 256)) =
                            make_float2(v0, v1);
                    } else {
                        float2 bv = *reinterpret_cast<const float2*>(b_attn + (col - 656));
                        v0 += bv.x; v1 += bv.y;
                        *reinterpret_cast<float2*>(OA + (size_t)row * OA_LD + 400 + (col - 656)) =
                            make_float2(v0, v1);
                    }
                } else {
                    float2 bv = *reinterpret_cast<const float2*>(bias + col);
                    v0 += bv.x; v1 += bv.y;
                    if (EPI == EP_RESID) {
                        float2 r = *reinterpret_cast<const float2*>(Res + (size_t)row * ldc + col);
                        v0 += r.x; v1 += r.y;
                        *reinterpret_cast<float2*>(Cout + (size_t)row * ldc + col) =
                            make_float2(v0, v1);
                    }
                    if (EPI == EP_GELU) {
                        v0 = gelu_exact(v0);
                        v1 = gelu_exact(v1);
                        *reinterpret_cast<__half2*>(OutH + (size_t)row * ldc + col) =
                            __floats2half2_rn(v0, v1);
                    }
                }
            }
        }
    }
}

// ======== sampling v3: warp = (token, 4 heads); 8 lanes/head ================
// lane: xsel = (hl>>2) picks x-tap (x0 / x0+1); c4 = hl&3 picks 16B channel
// slice. Each lane: 1 LDG.128 per row per point. Left/right x partials merge
// with one shfl_xor(4) after the 25-point loop. half2 blend, fp32 flush /5 pts.
__global__ void __launch_bounds__(256) sample_kernel(const float* __restrict__ refp)
{
    int warpId = blockIdx.x * 8 + (threadIdx.x >> 5);   // < NLTOK*2
    int lane = threadIdx.x & 31;
    int token = warpId >> 1;
    int hq = lane >> 3;                 // 0..3
    int hl = lane & 7;                  // 0..7
    int xsel = hl >> 2;                 // 0: x0, 1: x0+1
    int c4 = hl & 3;                    // channel slice (8 ch)
    int h = (warpId & 1) * 4 + hq;
    int n = token / LQ;

    const float* oa = g_oa + (size_t)token * OA_LD;

    // softmax over 25 logits with 8 lanes
    const float* lg = oa + 400 + h * NPTS;
    float l0 = __ldg(lg + hl);
    float l1 = __ldg(lg + hl + 8);
    float l2 = __ldg(lg + hl + 16);
    float l3 = (hl == 0) ? __ldg(lg + 24) : -1e30f;
    float mx = fmaxf(fmaxf(l0, l1), fmaxf(l2, l3));
#pragma unroll
    for (int o = 4; o > 0; o >>= 1)
        mx = fmaxf(mx, __shfl_xor_sync(0xffffffffu, mx, o, 8));
    float w0s = expf(l0 - mx), w1s = expf(l1 - mx), w2s = expf(l2 - mx);
    float w3s = (hl == 0) ? expf(l3 - mx) : 0.0f;
    float ssum = w0s + w1s + w2s + w3s;
#pragma unroll
    for (int o = 4; o > 0; o >>= 1)
        ssum += __shfl_xor_sync(0xffffffffu, ssum, o, 8);
    float inv = 1.0f / ssum;
    w0s *= inv; w1s *= inv; w2s *= inv; w3s *= inv;

    float2 rp = __ldg(reinterpret_cast<const float2*>(refp) + token);
    float gxb = fmaf(rp.x, (float)WDIM, -0.5f);
    float gyb = fmaf(rp.y, (float)HDIM, -0.5f);

    const float2* offp = reinterpret_cast<const float2*>(oa + h * (NPTS * 2));
    const char* vb = reinterpret_cast<const char*>(
        g_val + ((size_t)(n * NHEADS + h) * LQ) * DH);

    float2 accF[4];
#pragma unroll
    for (int i = 0; i < 4; i++) accF[i] = make_float2(0.f, 0.f);

#pragma unroll 1
    for (int g = 0; g < 5; g++) {
        __half2 accH[4];
#pragma unroll
        for (int i = 0; i < 4; i++) accH[i] = __floats2half2_rn(0.f, 0.f);
#pragma unroll
        for (int pp = 0; pp < 5; pp++) {
            int p = g * 5 + pp;
            float2 o2 = __ldg(offp + p);
            float src = (p < 8) ? w0s : (p < 16) ? w1s : (p < 24) ? w2s : w3s;
            float aw = __shfl_sync(0xffffffffu, src, p & 7, 8);
            float gx = gxb + o2.x;
            float gy = gyb + o2.y;
            float fx0 = floorf(gx), fy0 = floorf(gy);
            float fx = gx - fx0, fy = gy - fy0;
            int x0 = (int)fx0, y0 = (int)fy0;
            float wx = xsel ? fx : (1.f - fx);
            float wr0 = wx * (1.f - fy) * aw;       // this lane's x-tap, row y0
            float wr1 = wx * fy * aw;               // row y0+1
            bool interior = ((unsigned)x0 <= (unsigned)(WDIM - 2)) &&
                            ((unsigned)y0 <= (unsigned)(HDIM - 2));
            if (__all_sync(0xffffffffu, interior)) {
                const char* pr = vb + (size_t)(y0 * WDIM + x0) * (DH * 2) + hl * 16;
                uint4 v0 = *reinterpret_cast<const uint4*>(pr);
                uint4 v1 = *reinterpret_cast<const uint4*>(pr + WDIM * DH * 2);
                __half2 h0 = __floats2half2_rn(wr0, wr0);
                __half2 h1 = __floats2half2_rn(wr1, wr1);
                accH[0] = __hfma2(*reinterpret_cast<__half2*>(&v0.x), h0, accH[0]);
                accH[1] = __hfma2(*reinterpret_cast<__half2*>(&v0.y), h0, accH[1]);
                accH[2] = __hfma2(*reinterpret_cast<__half2*>(&v0.z), h0, accH[2]);
                accH[3] = __hfma2(*reinterpret_cast<__half2*>(&v0.w), h0, accH[3]);
                accH[0] = __hfma2(*reinterpret_cast<__half2*>(&v1.x), h1, accH[0]);
                accH[1] = __hfma2(*reinterpret_cast<__half2*>(&v1.y), h1, accH[1]);
                accH[2] = __hfma2(*reinterpret_cast<__half2*>(&v1.z), h1, accH[2]);
                accH[3] = __hfma2(*reinterpret_cast<__half2*>(&v1.w), h1, accH[3]);
            } else {
                int xi = x0 + xsel;
                bool xv = (xi >= 0) && (xi < WDIM);
#pragma unroll
                for (int rr = 0; rr < 2; rr++) {
                    int yi = y0 + rr;
                    float w = rr ? wr1 : wr0;
                    if (xv && yi >= 0 && yi < HDIM) {
                        uint4 v = *reinterpret_cast<const uint4*>(
                            vb + (size_t)(yi * WDIM + xi) * (DH * 2) + c4 * 16);
                        float2 f0 = __half22float2(*reinterpret_cast<__half2*>(&v.x));
                        float2 f1 = __half22float2(*reinterpret_cast<__half2*>(&v.y));
                        float2 f2 = __half22float2(*reinterpret_cast<__half2*>(&v.z));
                        float2 f3 = __half22float2(*reinterpret_cast<__half2*>(&v.w));
                        accF[0].x = fmaf(w, f0.x, accF[0].x);
                        accF[0].y = fmaf(w, f0.y, accF[0].y);
                        accF[1].x = fmaf(w, f1.x, accF[1].x);
                        accF[1].y = fmaf(w, f1.y, accF[1].y);
                        accF[2].x = fmaf(w, f2.x, accF[2].x);
                        accF[2].y = fmaf(w, f2.y, accF[2].y);
                        accF[3].x = fmaf(w, f3.x, accF[3].x);
                        accF[3].y = fmaf(w, f3.y, accF[3].y);
                    }
                }
            }
        }
#pragma unroll
        for (int i = 0; i < 4; i++) {
            float2 f = __half22float2(accH[i]);
            accF[i].x += f.x;
            accF[i].y += f.y;
        }
    }

    // merge x0 (lanes 0-3) with x0+1 (lanes 4-7)
#pragma unroll
    for (int i = 0; i < 4; i++) {
        accF[i].x += __shfl_xor_sync(0xffffffffu, accF[i].x, 4);
        accF[i].y += __shfl_xor_sync(0xffffffffu, accF[i].y, 4);
    }
    if (xsel == 0) {
        __half2 o0 = __floats2half2_rn(accF[0].x, accF[0].y);
        __half2 o1 = __floats2half2_rn(accF[1].x, accF[1].y);
        __half2 o2h = __floats2half2_rn(accF[2].x, accF[2].y);
        __half2 o3 = __floats2half2_rn(accF[3].x, accF[3].y);
        uint4 ov;
        ov.x = *reinterpret_cast<uint32_t*>(&o0);
        ov.y = *reinterpret_cast<uint32_t*>(&o1);
        ov.z = *reinterpret_cast<uint32_t*>(&o2h);
        ov.w = *reinterpret_cast<uint32_t*>(&o3);
        *reinterpret_cast<uint4*>(g_at + (size_t)token * CDIM + h * DH + c4 * 8) = ov;
    }
}

// ================= launch =================
extern "C" void kernel_launch(void* const* d_in, const int* in_sizes, int n_in,
                              void* d_out, int out_size)
{
    (void)in_sizes; (void)n_in; (void)out_size;
    const float* x      = (const float*)d_in[0];
    const float* refp   = (const float*)d_in[1];
    const float* ln1g   = (const float*)d_in[4];
    const float* ln1b   = (const float*)d_in[5];
    const float* w_off  = (const float*)d_in[6];
    const float* b_off  = (const float*)d_in[7];
    const float* w_attn = (const float*)d_in[8];
    const float* b_attn = (const float*)d_in[9];
    const float* w_val  = (const float*)d_in[10];
    const float* b_val  = (const float*)d_in[11];
    const float* w_out  = (const float*)d_in[12];
    const float* b_out  = (const float*)d_in[13];
    const float* ln2g   = (const float*)d_in[14];
    const float* ln2b   = (const float*)d_in[15];
    const float* w_fc1  = (const float*)d_in[16];
    const float* b_fc1  = (const float*)d_in[17];
    const float* w_fc2  = (const float*)d_in[18];
    const float* b_fc2  = (const float*)d_in[19];
    float* out = (float*)d_out;

    __half *q, *at, *q2, *h1, *wq, *wu, *w1, *w2, *pval;
    float *poa, *px1;
    cudaGetSymbolAddress((void**)&q,  g_q);   cudaGetSymbolAddress((void**)&at, g_at);
    cudaGetSymbolAddress((void**)&q2, g_q2);  cudaGetSymbolAddress((void**)&h1, g_h1);
    cudaGetSymbolAddress((void**)&wq, g_wq);  cudaGetSymbolAddress((void**)&wu, g_wu);
    cudaGetSymbolAddress((void**)&w1, g_w1);  cudaGetSymbolAddress((void**)&w2, g_w2);
    cudaGetSymbolAddress((void**)&pval, g_val);
    cudaGetSymbolAddress((void**)&poa,  g_oa);
    cudaGetSymbolAddress((void**)&px1,  g_x1);

    const int SM_TOT = NSTAGE * STAGE_BYTES;   // 72KB
    cudaFuncSetAttribute(mm_mma<EP_QKV>,   cudaFuncAttributeMaxDynamicSharedMemorySize, SM_TOT);
    cudaFuncSetAttribute(mm_mma<EP_RESID>, cudaFuncAttributeMaxDynamicSharedMemorySize, SM_TOT);
    cudaFuncSetAttribute(mm_mma<EP_GELU>,  cudaFuncAttributeMaxDynamicSharedMemorySize, SM_TOT);

    dim3 blk(256);
    const int MT = NLTOK / 128;   // 144

    wprep_all<<<808, blk>>>(w_val, w_off, w_attn, w_out, w_fc1, w_fc2, wq, wu, w1, w2);
    ln_kernel<<<NLTOK / 8, blk>>>(x, ln1g, ln1b, q);
    mm_mma<EP_QKV><<<dim3(14, MT), blk, SM_TOT>>>(q, wq, b_val, nullptr, nullptr, pval,
                                                  b_off, b_attn, poa, 256, 856, 0);
    sample_kernel<<<(NLTOK * 2) / 8, blk>>>(refp);
    mm_mma<EP_RESID><<<dim3(4, MT), blk, SM_TOT>>>(at, wu, b_out, px1, x, nullptr,
                                                   nullptr, nullptr, nullptr, 256, 256, 256);
    ln_kernel<<<NLTOK / 8, blk>>>(px1, ln2g, ln2b, q2);
    mm_mma<EP_GELU><<<dim3(16, MT), blk, SM_TOT>>>(q2, w1, b_fc1, nullptr, nullptr, h1,
                                                   nullptr, nullptr, nullptr, 256, 1024, 1024);
    mm_mma<EP_RESID><<<dim3(4, MT), blk, SM_TOT>>>(h1, w2, b_fc2, out, px1, nullptr,
                                                   nullptr, nullptr, nullptr, 1024, 256, 256);
}

// round 12
// speedup vs baseline: 1.0783x; 1.0783x over previous
#include <cuda_runtime.h>
#include <cuda_fp16.h>
#include <cstdint>
#include <math.h>

// Problem constants
#define NBATCH 2
#define HDIM   96
#define WDIM   96
#define CDIM   256
#define NHEADS 8
#define NPTS   25
#define DH     32
#define HIDDIM 1024
#define LQ     (HDIM*WDIM)      // 9216
#define NLTOK  (NBATCH*LQ)      // 18432
#define NQKV   896
#define OA_LD  600              // combined off(400)+attn(200) row stride

// ================= scratch (device globals, no allocation) =================
__device__ __align__(16) __half g_q  [NLTOK*CDIM];
__device__ __align__(16) __half g_at [NLTOK*CDIM];
__device__ __align__(16) __half g_q2 [NLTOK*CDIM];
__device__ __align__(16) __half g_h1 [NLTOK*HIDDIM];
__device__ __align__(16) __half g_val[NLTOK*CDIM];      // value [n,h,l,d], fp16
__device__ __align__(16) float  g_oa [NLTOK*OA_LD];
__device__ __align__(16) float  g_x1 [NLTOK*CDIM];
__device__ __align__(16) __half g_wq [NQKV*256];
__device__ __align__(16) __half g_wu [256*256];
__device__ __align__(16) __half g_w1 [1024*256];
__device__ __align__(16) __half g_w2 [256*1024];

// ================= low-level helpers ==================
__device__ __forceinline__ uint32_t smem_u32(const void* p) {
    uint32_t a;
    asm("{ .reg .u64 t; cvta.to.shared.u64 t, %1; cvt.u32.u64 %0, t; }" : "=r"(a) : "l"(p));
    return a;
}
__device__ __forceinline__ void cp16(uint32_t s, const void* g) {
    asm volatile("cp.async.cg.shared.global [%0], [%1], 16;" :: "r"(s), "l"(g));
}
#define CP_COMMIT() asm volatile("cp.async.commit_group;" ::: "memory")
#define CP_WAIT(n)  asm volatile("cp.async.wait_group %0;" :: "n"(n) : "memory")

__device__ __forceinline__ void ldm4(uint32_t* r, uint32_t addr) {
    asm volatile("ldmatrix.sync.aligned.m8n8.x4.shared.b16 {%0,%1,%2,%3}, [%4];"
                 : "=r"(r[0]), "=r"(r[1]), "=r"(r[2]), "=r"(r[3]) : "r"(addr));
}
__device__ __forceinline__ void mma_f16(float* d, const uint32_t* a, const uint32_t* b) {
    asm volatile("mma.sync.aligned.m16n8k16.row.col.f32.f16.f16.f32 "
                 "{%0,%1,%2,%3}, {%4,%5,%6,%7}, {%8,%9}, {%0,%1,%2,%3};"
                 : "+f"(d[0]), "+f"(d[1]), "+f"(d[2]), "+f"(d[3])
                 : "r"(a[0]), "r"(a[1]), "r"(a[2]), "r"(a[3]), "r"(b[0]), "r"(b[1]));
}

// ========== single mega weight-prep ========
__global__ void __launch_bounds__(256) wprep_all(const float* __restrict__ w_val,
                                                 const float* __restrict__ w_off,
                                                 const float* __restrict__ w_attn,
                                                 const float* __restrict__ w_out,
                                                 const float* __restrict__ w_fc1,
                                                 const float* __restrict__ w_fc2,
                                                 __half* __restrict__ wq,
                                                 __half* __restrict__ wu,
                                                 __half* __restrict__ w1,
                                                 __half* __restrict__ w2)
{
    int t = blockIdx.x;
    const float* src; __half* dst;
    int row0, K, N, Nallot, ktiles;
    if      (t < 64)  { src=w_val;  dst=wq; row0=0;   K=256;  N=256;  Nallot=256;  ktiles=8;  t -= 0; }
    else if (t < 168) { src=w_off;  dst=wq; row0=256; K=256;  N=400;  Nallot=400;  ktiles=8;  t -= 64; }
    else if (t < 232) { src=w_attn; dst=wq; row0=656; K=256;  N=200;  Nallot=240;  ktiles=8;  t -= 168; }
    else if (t < 296) { src=w_out;  dst=wu; row0=0;   K=256;  N=256;  Nallot=256;  ktiles=8;  t -= 232; }
    else if (t < 552) { src=w_fc1;  dst=w1; row0=0;   K=256;  N=1024; Nallot=1024; ktiles=8;  t -= 296; }
    else              { src=w_fc2;  dst=w2; row0=0;   K=1024; N=256;  Nallot=256;  ktiles=32; t -= 552; }
    int kt = t % ktiles, nt = t / ktiles;
    int k0 = kt * 32, n0 = nt * 32;

    __shared__ float s[32][33];
    int tx = threadIdx.x & 31, ty = threadIdx.x >> 5;
#pragma unroll
    for (int j = ty; j < 32; j += 8) {
        int n = n0 + tx;
        s[j][tx] = (n < N) ? src[(size_t)(k0 + j) * N + n] : 0.0f;
    }
    __syncthreads();
#pragma unroll
    for (int j = ty; j < 32; j += 8) {
        int n = n0 + j;
        if (n < Nallot)
            dst[(size_t)(row0 + n) * K + k0 + tx] = __float2half(s[tx][j]);
    }
}

// ================= LayerNorm ==========================
__global__ void __launch_bounds__(256) ln_kernel(const float* __restrict__ x,
                                                 const float* __restrict__ gam,
                                                 const float* __restrict__ bet,
                                                 __half* __restrict__ o)
{
    int warp = threadIdx.x >> 5, lane = threadIdx.x & 31;
    int token = blockIdx.x * 8 + warp;
    const float4* x4 = reinterpret_cast<const float4*>(x) + (size_t)token * 64;
    float4 v0 = x4[lane * 2];
    float4 v1 = x4[lane * 2 + 1];
    float s  = v0.x + v0.y + v0.z + v0.w + v1.x + v1.y + v1.z + v1.w;
    float sq = v0.x*v0.x + v0.y*v0.y + v0.z*v0.z + v0.w*v0.w
             + v1.x*v1.x + v1.y*v1.y + v1.z*v1.z + v1.w*v1.w;
#pragma unroll
    for (int of = 16; of > 0; of >>= 1) {
        s  += __shfl_xor_sync(0xffffffffu, s,  of);
        sq += __shfl_xor_sync(0xffffffffu, sq, of);
    }
    float mean = s * (1.0f / CDIM);
    float var  = sq * (1.0f / CDIM) - mean * mean;
    float rstd = rsqrtf(var + 1e-5f);
    const float4* g4 = reinterpret_cast<const float4*>(gam);
    const float4* b4 = reinterpret_cast<const float4*>(bet);
    float r[8];
    {
        float4 ga = g4[lane * 2],     ba = b4[lane * 2];
        float4 gb = g4[lane * 2 + 1], bb = b4[lane * 2 + 1];
        r[0] = (v0.x - mean) * rstd * ga.x + ba.x;
        r[1] = (v0.y - mean) * rstd * ga.y + ba.y;
        r[2] = (v0.z - mean) * rstd * ga.z + ba.z;
        r[3] = (v0.w - mean) * rstd * ga.w + ba.w;
        r[4] = (v1.x - mean) * rstd * gb.x + bb.x;
        r[5] = (v1.y - mean) * rstd * gb.y + bb.y;
        r[6] = (v1.z - mean) * rstd * gb.z + bb.z;
        r[7] = (v1.w - mean) * rstd * gb.w + bb.w;
    }
    size_t base = (size_t)token * CDIM + lane * 8;
#pragma unroll
    for (int i = 0; i < 8; i += 2)
        *reinterpret_cast<__half2*>(o + base + i) =
            __floats2half2_rn(r[i], r[i + 1]);
}

// ================= warp-MMA GEMM (2-stage cp.async) =========================
enum { EP_QKV = 0, EP_RESID = 2, EP_GELU = 3 };

__device__ __forceinline__ float gelu_exact(float v) {
    return 0.5f * v * (1.0f + erff(v * 0.70710678118654752f));
}

#define STAGE_BYTES 24576
#define B_OFF       16384

template <int EPI>
__global__ void __launch_bounds__(256) mm_mma(const __half* __restrict__ A,
                                              const __half* __restrict__ B,
                                              const float* __restrict__ bias,
                                              float* __restrict__ Cout,
                                              const float* __restrict__ Res,
                                              __half* __restrict__ OutH,
                                              const float* __restrict__ b_off,
                                              const float* __restrict__ b_attn,
                                              float* __restrict__ OA,
                                              int K, int Nvalid, int ldc)
{
    extern __shared__ __align__(128) char smem[];
    const uint32_t sb = smem_u32(smem);
    const int tid = threadIdx.x;
    const int wid = tid >> 5, l = tid & 31;
    const int wm = wid & 3, wn = wid >> 2;
    const int m0 = blockIdx.y * 128, n0 = blockIdx.x * 64;

    float acc[2][4][4];
#pragma unroll
    for (int i = 0; i < 2; i++)
#pragma unroll
        for (int j = 0; j < 4; j++)
#pragma unroll
            for (int q = 0; q < 4; q++) acc[i][j][q] = 0.0f;

    const int KC = K >> 6;

    auto load_stage = [&](int kcidx) {
        int k0 = kcidx << 6;
        uint32_t st = sb + (kcidx & 1) * STAGE_BYTES;
#pragma unroll
        for (int i = 0; i < 4; i++) {
            int id = tid + i * 256;
            int r = id >> 3, c = id & 7;
            cp16(st + r * 128 + ((c ^ (r & 7)) << 4),
                 A + (size_t)(m0 + r) * K + k0 + c * 8);
        }
#pragma unroll
        for (int i = 0; i < 2; i++) {
            int id = tid + i * 256;
            int r = id >> 3, c = id & 7;
            cp16(st + B_OFF + r * 128 + ((c ^ (r & 7)) << 4),
                 B + (size_t)(n0 + r) * K + k0 + c * 8);
        }
        CP_COMMIT();
    };

    load_stage(0);

    const int rowA = wm * 32 + (l & 15);
    const int cxA  = l >> 4;
    const int rowB = wn * 32 + (l & 7) + ((l >> 4) << 3);
    const int cxB  = (l >> 3) & 1;

    for (int kc = 0; kc < KC; kc++) {
        if (kc + 1 < KC) {
            load_stage(kc + 1);
            CP_WAIT(1);
        } else {
            CP_WAIT(0);
        }
        __syncthreads();

        uint32_t ab = sb + (kc & 1) * STAGE_BYTES;
        uint32_t bb = ab + B_OFF;
#pragma unroll
        for (int ks = 0; ks < 4; ks++) {
            uint32_t a[2][4], b[2][4];
#pragma unroll
            for (int mt = 0; mt < 2; mt++) {
                int row = rowA + mt * 16;
                ldm4(a[mt], ab + row * 128 + (((ks * 2 + cxA) ^ (row & 7)) << 4));
            }
#pragma unroll
            for (int ntp = 0; ntp < 2; ntp++) {
                int row = rowB + ntp * 16;
                ldm4(b[ntp], bb + row * 128 + (((ks * 2 + cxB) ^ (row & 7)) << 4));
            }
#pragma unroll
            for (int mt = 0; mt < 2; mt++)
#pragma unroll
                for (int nt = 0; nt < 4; nt++)
                    mma_f16(acc[mt][nt], a[mt], &b[nt >> 1][(nt & 1) * 2]);
        }
        __syncthreads();
    }

    // ---- epilogue ----
#pragma unroll
    for (int mt = 0; mt < 2; mt++) {
#pragma unroll
        for (int nt = 0; nt < 4; nt++) {
            int col = n0 + wn * 32 + nt * 8 + (l & 3) * 2;
            if (col >= Nvalid) continue;
#pragma unroll
            for (int half = 0; half < 2; half++) {
                int row = m0 + wm * 32 + mt * 16 + (l >> 2) + half * 8;
                float v0 = acc[mt][nt][half * 2];
                float v1 = acc[mt][nt][half * 2 + 1];
                if (EPI == EP_QKV) {
                    if (col < 256) {
                        float2 bv = *reinterpret_cast<const float2*>(bias + col);
                        v0 += bv.x; v1 += bv.y;
                        int n = row / LQ, li = row - n * LQ;
                        int h = col >> 5, d = col & 31;
                        *reinterpret_cast<__half2*>(OutH +
                            ((size_t)((n * NHEADS + h) * LQ + li)) * DH + d) =
                            __floats2half2_rn(v0, v1);
                    } else if (col < 656) {
                        float2 bv = *reinterpret_cast<const float2*>(b_off + (col - 256));
                        v0 += bv.x; v1 += bv.y;
                        *reinterpret_cast<float2*>(OA + (size_t)row * OA_LD + (col - 256)) =
                            make_float2(v0, v1);
                    } else {
                        float2 bv = *reinterpret_cast<const float2*>(b_attn + (col - 656));
                        v0 += bv.x; v1 += bv.y;
                        *reinterpret_cast<float2*>(OA + (size_t)row * OA_LD + 400 + (col - 656)) =
                            make_float2(v0, v1);
                    }
                } else {
                    float2 bv = *reinterpret_cast<const float2*>(bias + col);
                    v0 += bv.x; v1 += bv.y;
                    if (EPI == EP_RESID) {
                        float2 r = *reinterpret_cast<const float2*>(Res + (size_t)row * ldc + col);
                        v0 += r.x; v1 += r.y;
                        *reinterpret_cast<float2*>(Cout + (size_t)row * ldc + col) =
                            make_float2(v0, v1);
                    }
                    if (EPI == EP_GELU) {
                        v0 = gelu_exact(v0);
                        v1 = gelu_exact(v1);
                        *reinterpret_cast<__half2*>(OutH + (size_t)row * ldc + col) =
                            __floats2half2_rn(v0, v1);
                    }
                }
            }
        }
    }
}

// ======== sampling v2 (R10 config) + full unroll + __expf ===================
__global__ void __launch_bounds__(256) sample_kernel(const float* __restrict__ refp)
{
    int warpId = blockIdx.x * 8 + (threadIdx.x >> 5);   // < NLTOK*2
    int lane = threadIdx.x & 31;
    int token = warpId >> 1;
    int hq = lane >> 3;                 // 0..3
    int hl = lane & 7;                  // 0..7 -> channels hl*4 .. hl*4+3
    int h = (warpId & 1) * 4 + hq;
    int n = token / LQ;

    const float* oa = g_oa + (size_t)token * OA_LD;

    // softmax over 25 logits with 8 lanes: lane holds p = hl, hl+8, hl+16, (24)
    const float* lg = oa + 400 + h * NPTS;
    float l0 = __ldg(lg + hl);
    float l1 = __ldg(lg + hl + 8);
    float l2 = __ldg(lg + hl + 16);
    float l3 = (hl == 0) ? __ldg(lg + 24) : -1e30f;
    float mx = fmaxf(fmaxf(l0, l1), fmaxf(l2, l3));
#pragma unroll
    for (int o = 4; o > 0; o >>= 1)
        mx = fmaxf(mx, __shfl_xor_sync(0xffffffffu, mx, o, 8));
    float w0 = __expf(l0 - mx), w1 = __expf(l1 - mx), w2 = __expf(l2 - mx);
    float w3 = (hl == 0) ? __expf(l3 - mx) : 0.0f;
    float ssum = w0 + w1 + w2 + w3;
#pragma unroll
    for (int o = 4; o > 0; o >>= 1)
        ssum += __shfl_xor_sync(0xffffffffu, ssum, o, 8);
    float inv = 1.0f / ssum;
    w0 *= inv; w1 *= inv; w2 *= inv; w3 *= inv;

    float2 rp = __ldg(reinterpret_cast<const float2*>(refp) + token);
    float gxb = fmaf(rp.x, (float)WDIM, -0.5f);
    float gyb = fmaf(rp.y, (float)HDIM, -0.5f);

    const float2* offp = reinterpret_cast<const float2*>(oa + h * (NPTS * 2));
    const char* vbase = reinterpret_cast<const char*>(
        g_val + ((size_t)(n * NHEADS + h) * LQ) * DH) + hl * 8;

    float2 accA = make_float2(0.f, 0.f);
    float2 accB = make_float2(0.f, 0.f);
#pragma unroll
    for (int p = 0; p < NPTS; p++) {
        float2 o2 = __ldg(offp + p);
        float src = (p < 8) ? w0 : (p < 16) ? w1 : (p < 24) ? w2 : w3;
        float aw = __shfl_sync(0xffffffffu, src, p & 7, 8);
        float gx = gxb + o2.x;
        float gy = gyb + o2.y;
        float fx0 = floorf(gx), fy0 = floorf(gy);
        float fx = gx - fx0, fy = gy - fy0;
        int x0 = (int)fx0, y0 = (int)fy0;
        float t0 = (1.f - fy) * aw, t1 = fy * aw;
        float w00 = (1.f - fx) * t0, w10 = fx * t0;
        float w01 = (1.f - fx) * t1, w11 = fx * t1;
        bool interior = ((unsigned)x0 <= (unsigned)(WDIM - 2)) &&
                        ((unsigned)y0 <= (unsigned)(HDIM - 2));
        if (__all_sync(0xffffffffu, interior)) {
            const char* p00 = vbase + (y0 * WDIM + x0) * (DH * 2);
            uint2 v00 = *reinterpret_cast<const uint2*>(p00);
            uint2 v10 = *reinterpret_cast<const uint2*>(p00 + DH * 2);
            uint2 v01 = *reinterpret_cast<const uint2*>(p00 + WDIM * DH * 2);
            uint2 v11 = *reinterpret_cast<const uint2*>(p00 + (WDIM + 1) * DH * 2);
            __half2 h00 = __floats2half2_rn(w00, w00);
            __half2 h10 = __floats2half2_rn(w10, w10);
            __half2 h01 = __floats2half2_rn(w01, w01);
            __half2 h11 = __floats2half2_rn(w11, w11);
            __half2 sA = __hmul2(*reinterpret_cast<__half2*>(&v00.x), h00);
            __half2 sB = __hmul2(*reinterpret_cast<__half2*>(&v00.y), h00);
            sA = __hfma2(*reinterpret_cast<__half2*>(&v10.x), h10, sA);
            sB = __hfma2(*reinterpret_cast<__half2*>(&v10.y), h10, sB);
            sA = __hfma2(*reinterpret_cast<__half2*>(&v01.x), h01, sA);
            sB = __hfma2(*reinterpret_cast<__half2*>(&v01.y), h01, sB);
            sA = __hfma2(*reinterpret_cast<__half2*>(&v11.x), h11, sA);
            sB = __hfma2(*reinterpret_cast<__half2*>(&v11.y), h11, sB);
            float2 fA = __half22float2(sA), fB = __half22float2(sB);
            accA.x += fA.x; accA.y += fA.y;
            accB.x += fB.x; accB.y += fB.y;
        } else {
            bool xv0 = (x0 >= 0) && (x0 < WDIM);
            bool xv1 = (x0 + 1 >= 0) && (x0 + 1 < WDIM);
            bool yv0 = (y0 >= 0) && (y0 < HDIM);
            bool yv1 = (y0 + 1 >= 0) && (y0 + 1 < HDIM);
#pragma unroll
            for (int tp = 0; tp < 4; tp++) {
                int xi = x0 + (tp & 1), yi = y0 + (tp >> 1);
                bool valid = (tp & 1 ? xv1 : xv0) && (tp >> 1 ? yv1 : yv0);
                float w = (tp == 0) ? w00 : (tp == 1) ? w10 : (tp == 2) ? w01 : w11;
                if (valid) {
                    uint2 v = *reinterpret_cast<const uint2*>(
                        vbase + (yi * WDIM + xi) * (DH * 2));
                    float2 fA = __half22float2(*reinterpret_cast<__half2*>(&v.x));
                    float2 fB = __half22float2(*reinterpret_cast<__half2*>(&v.y));
                    accA.x = fmaf(w, fA.x, accA.x);
                    accA.y = fmaf(w, fA.y, accA.y);
                    accB.x = fmaf(w, fB.x, accB.x);
                    accB.y = fmaf(w, fB.y, accB.y);
                }
            }
        }
    }
    __half2 oA = __floats2half2_rn(accA.x, accA.y);
    __half2 oB = __floats2half2_rn(accB.x, accB.y);
    uint2 ov;
    ov.x = *reinterpret_cast<uint32_t*>(&oA);
    ov.y = *reinterpret_cast<uint32_t*>(&oB);
    *reinterpret_cast<uint2*>(g_at + (size_t)token * CDIM + h * DH + hl * 4) = ov;
}

// ================= launch =================
extern "C" void kernel_launch(void* const* d_in, const int* in_sizes, int n_in,
                              void* d_out, int out_size)
{
    (void)in_sizes; (void)n_in; (void)out_size;
    const float* x      = (const float*)d_in[0];
    const float* refp   = (const float*)d_in[1];
    const float* ln1g   = (const float*)d_in[4];
    const float* ln1b   = (const float*)d_in[5];
    const float* w_off  = (const float*)d_in[6];
    const float* b_off  = (const float*)d_in[7];
    const float* w_attn = (const float*)d_in[8];
    const float* b_attn = (const float*)d_in[9];
    const float* w_val  = (const float*)d_in[10];
    const float* b_val  = (const float*)d_in[11];
    const float* w_out  = (const float*)d_in[12];
    const float* b_out  = (const float*)d_in[13];
    const float* ln2g   = (const float*)d_in[14];
    const float* ln2b   = (const float*)d_in[15];
    const float* w_fc1  = (const float*)d_in[16];
    const float* b_fc1  = (const float*)d_in[17];
    const float* w_fc2  = (const float*)d_in[18];
    const float* b_fc2  = (const float*)d_in[19];
    float* out = (float*)d_out;

    __half *q, *at, *q2, *h1, *wq, *wu, *w1, *w2, *pval;
    float *poa, *px1;
    cudaGetSymbolAddress((void**)&q,  g_q);   cudaGetSymbolAddress((void**)&at, g_at);
    cudaGetSymbolAddress((void**)&q2, g_q2);  cudaGetSymbolAddress((void**)&h1, g_h1);
    cudaGetSymbolAddress((void**)&wq, g_wq);  cudaGetSymbolAddress((void**)&wu, g_wu);
    cudaGetSymbolAddress((void**)&w1, g_w1);  cudaGetSymbolAddress((void**)&w2, g_w2);
    cudaGetSymbolAddress((void**)&pval, g_val);
    cudaGetSymbolAddress((void**)&poa,  g_oa);
    cudaGetSymbolAddress((void**)&px1,  g_x1);

    const int SM_TOT = 2 * STAGE_BYTES;   // 48KB
    cudaFuncSetAttribute(mm_mma<EP_QKV>,   cudaFuncAttributeMaxDynamicSharedMemorySize, SM_TOT);
    cudaFuncSetAttribute(mm_mma<EP_RESID>, cudaFuncAttributeMaxDynamicSharedMemorySize, SM_TOT);
    cudaFuncSetAttribute(mm_mma<EP_GELU>,  cudaFuncAttributeMaxDynamicSharedMemorySize, SM_TOT);

    dim3 blk(256);
    const int MT = NLTOK / 128;   // 144

    wprep_all<<<808, blk>>>(w_val, w_off, w_attn, w_out, w_fc1, w_fc2, wq, wu, w1, w2);
    ln_kernel<<<NLTOK / 8, blk>>>(x, ln1g, ln1b, q);
    mm_mma<EP_QKV><<<dim3(14, MT), blk, SM_TOT>>>(q, wq, b_val, nullptr, nullptr, pval,
                                                  b_off, b_attn, poa, 256, 856, 0);
    sample_kernel<<<(NLTOK * 2) / 8, blk>>>(refp);
    mm_mma<EP_RESID><<<dim3(4, MT), blk, SM_TOT>>>(at, wu, b_out, px1, x, nullptr,
                                                   nullptr, nullptr, nullptr, 256, 256, 256);
    ln_kernel<<<NLTOK / 8, blk>>>(px1, ln2g, ln2b, q2);
    mm_mma<EP_GELU><<<dim3(16, MT), blk, SM_TOT>>>(q2, w1, b_fc1, nullptr, nullptr, h1,
                                                   nullptr, nullptr, nullptr, 256, 1024, 1024);
    mm_mma<EP_RESID><<<dim3(4, MT), blk, SM_TOT>>>(h1, w2, b_fc2, out, px1, nullptr,
                                                   nullptr, nullptr, nullptr, 1024, 256, 256);
}

// round 13
// speedup vs baseline: 1.0934x; 1.0140x over previous
#include <cuda_runtime.h>
#include <cuda_fp16.h>
#include <cstdint>
#include <math.h>

// Problem constants
#define NBATCH 2
#define HDIM   96
#define WDIM   96
#define CDIM   256
#define NHEADS 8
#define NPTS   25
#define DH     32
#define HIDDIM 1024
#define LQ     (HDIM*WDIM)      // 9216
#define NLTOK  (NBATCH*LQ)      // 18432
#define NQKV   896
#define OA_LD  600              // combined off(400)+attn(200) row stride

// ================= scratch (device globals, no allocation) =================
__device__ __align__(16) __half g_q  [NLTOK*CDIM];
__device__ __align__(16) __half g_at [NLTOK*CDIM];
__device__ __align__(16) __half g_q2 [NLTOK*CDIM];
__device__ __align__(16) __half g_h1 [NLTOK*HIDDIM];
__device__ __align__(16) __half g_val[NLTOK*CDIM];      // value [n,h,l,d], fp16
__device__ __align__(16) float  g_oa [NLTOK*OA_LD];
__device__ __align__(16) float  g_x1 [NLTOK*CDIM];
__device__ __align__(16) __half g_wq [NQKV*256];
__device__ __align__(16) __half g_wu [256*256];
__device__ __align__(16) __half g_w1 [1024*256];
__device__ __align__(16) __half g_w2 [256*1024];

// ================= low-level helpers ==================
__device__ __forceinline__ uint32_t smem_u32(const void* p) {
    uint32_t a;
    asm("{ .reg .u64 t; cvta.to.shared.u64 t, %1; cvt.u32.u64 %0, t; }" : "=r"(a) : "l"(p));
    return a;
}
__device__ __forceinline__ void cp16(uint32_t s, const void* g) {
    asm volatile("cp.async.cg.shared.global [%0], [%1], 16;" :: "r"(s), "l"(g));
}
#define CP_COMMIT() asm volatile("cp.async.commit_group;" ::: "memory")
#define CP_WAIT(n)  asm volatile("cp.async.wait_group %0;" :: "n"(n) : "memory")

__device__ __forceinline__ void ldm4(uint32_t* r, uint32_t addr) {
    asm volatile("ldmatrix.sync.aligned.m8n8.x4.shared.b16 {%0,%1,%2,%3}, [%4];"
                 : "=r"(r[0]), "=r"(r[1]), "=r"(r[2]), "=r"(r[3]) : "r"(addr));
}
__device__ __forceinline__ void mma_f16(float* d, const uint32_t* a, const uint32_t* b) {
    asm volatile("mma.sync.aligned.m16n8k16.row.col.f32.f16.f16.f32 "
                 "{%0,%1,%2,%3}, {%4,%5,%6,%7}, {%8,%9}, {%0,%1,%2,%3};"
                 : "+f"(d[0]), "+f"(d[1]), "+f"(d[2]), "+f"(d[3])
                 : "r"(a[0]), "r"(a[1]), "r"(a[2]), "r"(a[3]), "r"(b[0]), "r"(b[1]));
}

// ========== single mega weight-prep ========
__global__ void __launch_bounds__(256) wprep_all(const float* __restrict__ w_val,
                                                 const float* __restrict__ w_off,
                                                 const float* __restrict__ w_attn,
                                                 const float* __restrict__ w_out,
                                                 const float* __restrict__ w_fc1,
                                                 const float* __restrict__ w_fc2,
                                                 __half* __restrict__ wq,
                                                 __half* __restrict__ wu,
                                                 __half* __restrict__ w1,
                                                 __half* __restrict__ w2)
{
    int t = blockIdx.x;
    const float* src; __half* dst;
    int row0, K, N, Nallot, ktiles;
    if      (t < 64)  { src=w_val;  dst=wq; row0=0;   K=256;  N=256;  Nallot=256;  ktiles=8;  t -= 0; }
    else if (t < 168) { src=w_off;  dst=wq; row0=256; K=256;  N=400;  Nallot=400;  ktiles=8;  t -= 64; }
    else if (t < 232) { src=w_attn; dst=wq; row0=656; K=256;  N=200;  Nallot=240;  ktiles=8;  t -= 168; }
    else if (t < 296) { src=w_out;  dst=wu; row0=0;   K=256;  N=256;  Nallot=256;  ktiles=8;  t -= 232; }
    else if (t < 552) { src=w_fc1;  dst=w1; row0=0;   K=256;  N=1024; Nallot=1024; ktiles=8;  t -= 296; }
    else              { src=w_fc2;  dst=w2; row0=0;   K=1024; N=256;  Nallot=256;  ktiles=32; t -= 552; }
    int kt = t % ktiles, nt = t / ktiles;
    int k0 = kt * 32, n0 = nt * 32;

    __shared__ float s[32][33];
    int tx = threadIdx.x & 31, ty = threadIdx.x >> 5;
#pragma unroll
    for (int j = ty; j < 32; j += 8) {
        int n = n0 + tx;
        s[j][tx] = (n < N) ? src[(size_t)(k0 + j) * N + n] : 0.0f;
    }
    __syncthreads();
#pragma unroll
    for (int j = ty; j < 32; j += 8) {
        int n = n0 + j;
        if (n < Nallot)
            dst[(size_t)(row0 + n) * K + k0 + tx] = __float2half(s[tx][j]);
    }
}

// ================= LayerNorm ==========================
__global__ void __launch_bounds__(256) ln_kernel(const float* __restrict__ x,
                                                 const float* __restrict__ gam,
                                                 const float* __restrict__ bet,
                                                 __half* __restrict__ o)
{
    int warp = threadIdx.x >> 5, lane = threadIdx.x & 31;
    int token = blockIdx.x * 8 + warp;
    const float4* x4 = reinterpret_cast<const float4*>(x) + (size_t)token * 64;
    float4 v0 = x4[lane * 2];
    float4 v1 = x4[lane * 2 + 1];
    float s  = v0.x + v0.y + v0.z + v0.w + v1.x + v1.y + v1.z + v1.w;
    float sq = v0.x*v0.x + v0.y*v0.y + v0.z*v0.z + v0.w*v0.w
             + v1.x*v1.x + v1.y*v1.y + v1.z*v1.z + v1.w*v1.w;
#pragma unroll
    for (int of = 16; of > 0; of >>= 1) {
        s  += __shfl_xor_sync(0xffffffffu, s,  of);
        sq += __shfl_xor_sync(0xffffffffu, sq, of);
    }
    float mean = s * (1.0f / CDIM);
    float var  = sq * (1.0f / CDIM) - mean * mean;
    float rstd = rsqrtf(var + 1e-5f);
    const float4* g4 = reinterpret_cast<const float4*>(gam);
    const float4* b4 = reinterpret_cast<const float4*>(bet);
    float r[8];
    {
        float4 ga = g4[lane * 2],     ba = b4[lane * 2];
        float4 gb = g4[lane * 2 + 1], bb = b4[lane * 2 + 1];
        r[0] = (v0.x - mean) * rstd * ga.x + ba.x;
        r[1] = (v0.y - mean) * rstd * ga.y + ba.y;
        r[2] = (v0.z - mean) * rstd * ga.z + ba.z;
        r[3] = (v0.w - mean) * rstd * ga.w + ba.w;
        r[4] = (v1.x - mean) * rstd * gb.x + bb.x;
        r[5] = (v1.y - mean) * rstd * gb.y + bb.y;
        r[6] = (v1.z - mean) * rstd * gb.z + bb.z;
        r[7] = (v1.w - mean) * rstd * gb.w + bb.w;
    }
    size_t base = (size_t)token * CDIM + lane * 8;
#pragma unroll
    for (int i = 0; i < 8; i += 2)
        *reinterpret_cast<__half2*>(o + base + i) =
            __floats2half2_rn(r[i], r[i + 1]);
}

// ================= warp-MMA GEMM (BM=128, BN=128, BK=64, 2-stage) ===========
// 8 warps: wm = wid&3 (4 x 32 rows), wn = wid>>2 (2 x 64 cols).
// per-warp: mt 2 (16-row tiles) x nt 8 (8-col tiles), acc 64 fp32.
enum { EP_QKV = 0, EP_RESID = 2, EP_GELU = 3 };

__device__ __forceinline__ float gelu_exact(float v) {
    return 0.5f * v * (1.0f + erff(v * 0.70710678118654752f));
}

#define STAGE_BYTES 32768
#define B_OFF       16384

template <int EPI>
__global__ void __launch_bounds__(256) mm_mma(const __half* __restrict__ A,
                                              const __half* __restrict__ B,
                                              const float* __restrict__ bias,
                                              float* __restrict__ Cout,
                                              const float* __restrict__ Res,
                                              __half* __restrict__ OutH,
                                              const float* __restrict__ b_off,
                                              const float* __restrict__ b_attn,
                                              float* __restrict__ OA,
                                              int K, int Nvalid, int ldc)
{
    extern __shared__ __align__(128) char smem[];
    const uint32_t sb = smem_u32(smem);
    const int tid = threadIdx.x;
    const int wid = tid >> 5, l = tid & 31;
    const int wm = wid & 3, wn = wid >> 2;
    const int m0 = blockIdx.y * 128, n0 = blockIdx.x * 128;

    float acc[2][8][4];
#pragma unroll
    for (int i = 0; i < 2; i++)
#pragma unroll
        for (int j = 0; j < 8; j++)
#pragma unroll
            for (int q = 0; q < 4; q++) acc[i][j][q] = 0.0f;

    const int KC = K >> 6;

    auto load_stage = [&](int kcidx) {
        int k0 = kcidx << 6;
        uint32_t st = sb + (kcidx & 1) * STAGE_BYTES;
#pragma unroll
        for (int i = 0; i < 4; i++) {          // A: 128 rows
            int id = tid + i * 256;
            int r = id >> 3, c = id & 7;
            cp16(st + r * 128 + ((c ^ (r & 7)) << 4),
                 A + (size_t)(m0 + r) * K + k0 + c * 8);
        }
#pragma unroll
        for (int i = 0; i < 4; i++) {          // B: 128 rows
            int id = tid + i * 256;
            int r = id >> 3, c = id & 7;
            cp16(st + B_OFF + r * 128 + ((c ^ (r & 7)) << 4),
                 B + (size_t)(n0 + r) * K + k0 + c * 8);
        }
        CP_COMMIT();
    };

    load_stage(0);

    const int rowA = wm * 32 + (l & 15);
    const int cxA  = l >> 4;
    const int rowB = wn * 64 + (l & 7) + ((l >> 4) << 3);
    const int cxB  = (l >> 3) & 1;

    for (int kc = 0; kc < KC; kc++) {
        if (kc + 1 < KC) {
            load_stage(kc + 1);
            CP_WAIT(1);
        } else {
            CP_WAIT(0);
        }
        __syncthreads();

        uint32_t ab = sb + (kc & 1) * STAGE_BYTES;
        uint32_t bb = ab + B_OFF;
#pragma unroll
        for (int ks = 0; ks < 4; ks++) {
            uint32_t a[2][4], b[4][4];
#pragma unroll
            for (int mt = 0; mt < 2; mt++) {
                int row = rowA + mt * 16;
                ldm4(a[mt], ab + row * 128 + (((ks * 2 + cxA) ^ (row & 7)) << 4));
            }
#pragma unroll
            for (int ntp = 0; ntp < 4; ntp++) {
                int row = rowB + ntp * 16;
                ldm4(b[ntp], bb + row * 128 + (((ks * 2 + cxB) ^ (row & 7)) << 4));
            }
#pragma unroll
            for (int mt = 0; mt < 2; mt++)
#pragma unroll
                for (int nt = 0; nt < 8; nt++)
                    mma_f16(acc[mt][nt], a[mt], &b[nt >> 1][(nt & 1) * 2]);
        }
        __syncthreads();
    }

    // ---- epilogue ----
#pragma unroll
    for (int mt = 0; mt < 2; mt++) {
#pragma unroll
        for (int nt = 0; nt < 8; nt++) {
            int col = n0 + wn * 64 + nt * 8 + (l & 3) * 2;
            if (col >= Nvalid) continue;
#pragma unroll
            for (int half = 0; half < 2; half++) {
                int row = m0 + wm * 32 + mt * 16 + (l >> 2) + half * 8;
                float v0 = acc[mt][nt][half * 2];
                float v1 = acc[mt][nt][half * 2 + 1];
                if (EPI == EP_QKV) {
                    if (col < 256) {
                        float2 bv = *reinterpret_cast<const float2*>(bias + col);
                        v0 += bv.x; v1 += bv.y;
                        int n = row / LQ, li = row - n * LQ;
                        int h = col >> 5, d = col & 31;
                        *reinterpret_cast<__half2*>(OutH +
                            ((size_t)((n * NHEADS + h) * LQ + li)) * DH + d) =
                            __floats2half2_rn(v0, v1);
                    } else if (col < 656) {
                        float2 bv = *reinterpret_cast<const float2*>(b_off + (col - 256));
                        v0 += bv.x; v1 += bv.y;
                        *reinterpret_cast<float2*>(OA + (size_t)row * OA_LD + (col - 256)) =
                            make_float2(v0, v1);
                    } else {
                        float2 bv = *reinterpret_cast<const float2*>(b_attn + (col - 656));
                        v0 += bv.x; v1 += bv.y;
                        *reinterpret_cast<float2*>(OA + (size_t)row * OA_LD + 400 + (col - 656)) =
                            make_float2(v0, v1);
                    }
                } else {
                    float2 bv = *reinterpret_cast<const float2*>(bias + col);
                    v0 += bv.x; v1 += bv.y;
                    if (EPI == EP_RESID) {
                        float2 r = *reinterpret_cast<const float2*>(Res + (size_t)row * ldc + col);
                        v0 += r.x; v1 += r.y;
                        *reinterpret_cast<float2*>(Cout + (size_t)row * ldc + col) =
                            make_float2(v0, v1);
                    }
                    if (EPI == EP_GELU) {
                        v0 = gelu_exact(v0);
                        v1 = gelu_exact(v1);
                        *reinterpret_cast<__half2*>(OutH + (size_t)row * ldc + col) =
                            __floats2half2_rn(v0, v1);
                    }
                }
            }
        }
    }
}

// ======== sampling v2 (R12 config, unchanged) ===============================
__global__ void __launch_bounds__(256) sample_kernel(const float* __restrict__ refp)
{
    int warpId = blockIdx.x * 8 + (threadIdx.x >> 5);   // < NLTOK*2
    int lane = threadIdx.x & 31;
    int token = warpId >> 1;
    int hq = lane >> 3;                 // 0..3
    int hl = lane & 7;                  // 0..7 -> channels hl*4 .. hl*4+3
    int h = (warpId & 1) * 4 + hq;
    int n = token / LQ;

    const float* oa = g_oa + (size_t)token * OA_LD;

    const float* lg = oa + 400 + h * NPTS;
    float l0 = __ldg(lg + hl);
    float l1 = __ldg(lg + hl + 8);
    float l2 = __ldg(lg + hl + 16);
    float l3 = (hl == 0) ? __ldg(lg + 24) : -1e30f;
    float mx = fmaxf(fmaxf(l0, l1), fmaxf(l2, l3));
#pragma unroll
    for (int o = 4; o > 0; o >>= 1)
        mx = fmaxf(mx, __shfl_xor_sync(0xffffffffu, mx, o, 8));
    float w0 = __expf(l0 - mx), w1 = __expf(l1 - mx), w2 = __expf(l2 - mx);
    float w3 = (hl == 0) ? __expf(l3 - mx) : 0.0f;
    float ssum = w0 + w1 + w2 + w3;
#pragma unroll
    for (int o = 4; o > 0; o >>= 1)
        ssum += __shfl_xor_sync(0xffffffffu, ssum, o, 8);
    float inv = 1.0f / ssum;
    w0 *= inv; w1 *= inv; w2 *= inv; w3 *= inv;

    float2 rp = __ldg(reinterpret_cast<const float2*>(refp) + token);
    float gxb = fmaf(rp.x, (float)WDIM, -0.5f);
    float gyb = fmaf(rp.y, (float)HDIM, -0.5f);

    const float2* offp = reinterpret_cast<const float2*>(oa + h * (NPTS * 2));
    const char* vbase = reinterpret_cast<const char*>(
        g_val + ((size_t)(n * NHEADS + h) * LQ) * DH) + hl * 8;

    float2 accA = make_float2(0.f, 0.f);
    float2 accB = make_float2(0.f, 0.f);
#pragma unroll
    for (int p = 0; p < NPTS; p++) {
        float2 o2 = __ldg(offp + p);
        float src = (p < 8) ? w0 : (p < 16) ? w1 : (p < 24) ? w2 : w3;
        float aw = __shfl_sync(0xffffffffu, src, p & 7, 8);
        float gx = gxb + o2.x;
        float gy = gyb + o2.y;
        float fx0 = floorf(gx), fy0 = floorf(gy);
        float fx = gx - fx0, fy = gy - fy0;
        int x0 = (int)fx0, y0 = (int)fy0;
        float t0 = (1.f - fy) * aw, t1 = fy * aw;
        float w00 = (1.f - fx) * t0, w10 = fx * t0;
        float w01 = (1.f - fx) * t1, w11 = fx * t1;
        bool interior = ((unsigned)x0 <= (unsigned)(WDIM - 2)) &&
                        ((unsigned)y0 <= (unsigned)(HDIM - 2));
        if (__all_sync(0xffffffffu, interior)) {
            const char* p00 = vbase + (y0 * WDIM + x0) * (DH * 2);
            uint2 v00 = *reinterpret_cast<const uint2*>(p00);
            uint2 v10 = *reinterpret_cast<const uint2*>(p00 + DH * 2);
            uint2 v01 = *reinterpret_cast<const uint2*>(p00 + WDIM * DH * 2);
            uint2 v11 = *reinterpret_cast<const uint2*>(p00 + (WDIM + 1) * DH * 2);
            __half2 h00 = __floats2half2_rn(w00, w00);
            __half2 h10 = __floats2half2_rn(w10, w10);
            __half2 h01 = __floats2half2_rn(w01, w01);
            __half2 h11 = __floats2half2_rn(w11, w11);
            __half2 sA = __hmul2(*reinterpret_cast<__half2*>(&v00.x), h00);
            __half2 sB = __hmul2(*reinterpret_cast<__half2*>(&v00.y), h00);
            sA = __hfma2(*reinterpret_cast<__half2*>(&v10.x), h10, sA);
            sB = __hfma2(*reinterpret_cast<__half2*>(&v10.y), h10, sB);
            sA = __hfma2(*reinterpret_cast<__half2*>(&v01.x), h01, sA);
            sB = __hfma2(*reinterpret_cast<__half2*>(&v01.y), h01, sB);
            sA = __hfma2(*reinterpret_cast<__half2*>(&v11.x), h11, sA);
            sB = __hfma2(*reinterpret_cast<__half2*>(&v11.y), h11, sB);
            float2 fA = __half22float2(sA), fB = __half22float2(sB);
            accA.x += fA.x; accA.y += fA.y;
            accB.x += fB.x; accB.y += fB.y;
        } else {
            bool xv0 = (x0 >= 0) && (x0 < WDIM);
            bool xv1 = (x0 + 1 >= 0) && (x0 + 1 < WDIM);
            bool yv0 = (y0 >= 0) && (y0 < HDIM);
            bool yv1 = (y0 + 1 >= 0) && (y0 + 1 < HDIM);
#pragma unroll
            for (int tp = 0; tp < 4; tp++) {
                int xi = x0 + (tp & 1), yi = y0 + (tp >> 1);
                bool valid = (tp & 1 ? xv1 : xv0) && (tp >> 1 ? yv1 : yv0);
                float w = (tp == 0) ? w00 : (tp == 1) ? w10 : (tp == 2) ? w01 : w11;
                if (valid) {
                    uint2 v = *reinterpret_cast<const uint2*>(
                        vbase + (yi * WDIM + xi) * (DH * 2));
                    float2 fA = __half22float2(*reinterpret_cast<__half2*>(&v.x));
                    float2 fB = __half22float2(*reinterpret_cast<__half2*>(&v.y));
                    accA.x = fmaf(w, fA.x, accA.x);
                    accA.y = fmaf(w, fA.y, accA.y);
                    accB.x = fmaf(w, fB.x, accB.x);
                    accB.y = fmaf(w, fB.y, accB.y);
                }
            }
        }
    }
    __half2 oA = __floats2half2_rn(accA.x, accA.y);
    __half2 oB = __floats2half2_rn(accB.x, accB.y);
    uint2 ov;
    ov.x = *reinterpret_cast<uint32_t*>(&oA);
    ov.y = *reinterpret_cast<uint32_t*>(&oB);
    *reinterpret_cast<uint2*>(g_at + (size_t)token * CDIM + h * DH + hl * 4) = ov;
}

// ================= launch =================
extern "C" void kernel_launch(void* const* d_in, const int* in_sizes, int n_in,
                              void* d_out, int out_size)
{
    (void)in_sizes; (void)n_in; (void)out_size;
    const float* x      = (const float*)d_in[0];
    const float* refp   = (const float*)d_in[1];
    const float* ln1g   = (const float*)d_in[4];
    const float* ln1b   = (const float*)d_in[5];
    const float* w_off  = (const float*)d_in[6];
    const float* b_off  = (const float*)d_in[7];
    const float* w_attn = (const float*)d_in[8];
    const float* b_attn = (const float*)d_in[9];
    const float* w_val  = (const float*)d_in[10];
    const float* b_val  = (const float*)d_in[11];
    const float* w_out  = (const float*)d_in[12];
    const float* b_out  = (const float*)d_in[13];
    const float* ln2g   = (const float*)d_in[14];
    const float* ln2b   = (const float*)d_in[15];
    const float* w_fc1  = (const float*)d_in[16];
    const float* b_fc1  = (const float*)d_in[17];
    const float* w_fc2  = (const float*)d_in[18];
    const float* b_fc2  = (const float*)d_in[19];
    float* out = (float*)d_out;

    __half *q, *at, *q2, *h1, *wq, *wu, *w1, *w2, *pval;
    float *poa, *px1;
    cudaGetSymbolAddress((void**)&q,  g_q);   cudaGetSymbolAddress((void**)&at, g_at);
    cudaGetSymbolAddress((void**)&q2, g_q2);  cudaGetSymbolAddress((void**)&h1, g_h1);
    cudaGetSymbolAddress((void**)&wq, g_wq);  cudaGetSymbolAddress((void**)&wu, g_wu);
    cudaGetSymbolAddress((void**)&w1, g_w1);  cudaGetSymbolAddress((void**)&w2, g_w2);
    cudaGetSymbolAddress((void**)&pval, g_val);
    cudaGetSymbolAddress((void**)&poa,  g_oa);
    cudaGetSymbolAddress((void**)&px1,  g_x1);

    const int SM_TOT = 2 * STAGE_BYTES;   // 64KB
    cudaFuncSetAttribute(mm_mma<EP_QKV>,   cudaFuncAttributeMaxDynamicSharedMemorySize, SM_TOT);
    cudaFuncSetAttribute(mm_mma<EP_RESID>, cudaFuncAttributeMaxDynamicSharedMemorySize, SM_TOT);
    cudaFuncSetAttribute(mm_mma<EP_GELU>,  cudaFuncAttributeMaxDynamicSharedMemorySize, SM_TOT);

    dim3 blk(256);
    const int MT = NLTOK / 128;   // 144

    wprep_all<<<808, blk>>>(w_val, w_off, w_attn, w_out, w_fc1, w_fc2, wq, wu, w1, w2);
    ln_kernel<<<NLTOK / 8, blk>>>(x, ln1g, ln1b, q);
    mm_mma<EP_QKV><<<dim3(7, MT), blk, SM_TOT>>>(q, wq, b_val, nullptr, nullptr, pval,
                                                 b_off, b_attn, poa, 256, 856, 0);
    sample_kernel<<<(NLTOK * 2) / 8, blk>>>(refp);
    mm_mma<EP_RESID><<<dim3(2, MT), blk, SM_TOT>>>(at, wu, b_out, px1, x, nullptr,
                                                   nullptr, nullptr, nullptr, 256, 256, 256);
    ln_kernel<<<NLTOK / 8, blk>>>(px1, ln2g, ln2b, q2);
    mm_mma<EP_GELU><<<dim3(8, MT), blk, SM_TOT>>>(q2, w1, b_fc1, nullptr, nullptr, h1,
                                                  nullptr, nullptr, nullptr, 256, 1024, 1024);
    mm_mma<EP_RESID><<<dim3(2, MT), blk, SM_TOT>>>(h1, w2, b_fc2, out, px1, nullptr,
                                                   nullptr, nullptr, nullptr, 1024, 256, 256);
}

// round 15
// speedup vs baseline: 1.1661x; 1.0665x over previous
#include <cuda_runtime.h>
#include <cuda_fp16.h>
#include <cstdint>
#include <math.h>

// Problem constants
#define NBATCH 2
#define HDIM   96
#define WDIM   96
#define CDIM   256
#define NHEADS 8
#define NPTS   25
#define DH     32
#define HIDDIM 1024
#define LQ     (HDIM*WDIM)      // 9216
#define NLTOK  (NBATCH*LQ)      // 18432
#define NQKV   896
#define OA_LD  600              // combined off(400)+attn(200) row stride

// ================= scratch (device globals, no allocation) =================
__device__ __align__(16) __half g_q  [NLTOK*CDIM];
__device__ __align__(16) __half g_at [NLTOK*CDIM];
__device__ __align__(16) __half g_q2 [NLTOK*CDIM];
__device__ __align__(16) __half g_h1 [NLTOK*HIDDIM];
__device__ __align__(16) __half g_val[NLTOK*CDIM];      // value [n,h,l,d], fp16
__device__ __align__(16) float  g_oa [NLTOK*OA_LD];
__device__ __align__(16) float  g_x1 [NLTOK*CDIM];
__device__ __align__(16) __half g_wq [NQKV*256];
__device__ __align__(16) __half g_wu [256*256];
__device__ __align__(16) __half g_w1 [1024*256];
__device__ __align__(16) __half g_w2 [256*1024];

// ================= low-level helpers ==================
__device__ __forceinline__ uint32_t smem_u32(const void* p) {
    uint32_t a;
    asm("{ .reg .u64 t; cvta.to.shared.u64 t, %1; cvt.u32.u64 %0, t; }" : "=r"(a) : "l"(p));
    return a;
}
__device__ __forceinline__ void cp16(uint32_t s, const void* g) {
    asm volatile("cp.async.cg.shared.global [%0], [%1], 16;" :: "r"(s), "l"(g));
}
#define CP_COMMIT() asm volatile("cp.async.commit_group;" ::: "memory")
#define CP_WAIT(n)  asm volatile("cp.async.wait_group %0;" :: "n"(n) : "memory")

__device__ __forceinline__ void ldm4(uint32_t* r, uint32_t addr) {
    asm volatile("ldmatrix.sync.aligned.m8n8.x4.shared.b16 {%0,%1,%2,%3}, [%4];"
                 : "=r"(r[0]), "=r"(r[1]), "=r"(r[2]), "=r"(r[3]) : "r"(addr));
}
__device__ __forceinline__ void mma_f16(float* d, const uint32_t* a, const uint32_t* b) {
    asm volatile("mma.sync.aligned.m16n8k16.row.col.f32.f16.f16.f32 "
                 "{%0,%1,%2,%3}, {%4,%5,%6,%7}, {%8,%9}, {%0,%1,%2,%3};"
                 : "+f"(d[0]), "+f"(d[1]), "+f"(d[2]), "+f"(d[3])
                 : "r"(a[0]), "r"(a[1]), "r"(a[2]), "r"(a[3]), "r"(b[0]), "r"(b[1]));
}

// ========== single mega weight-prep ========
__global__ void __launch_bounds__(256) wprep_all(const float* __restrict__ w_val,
                                                 const float* __restrict__ w_off,
                                                 const float* __restrict__ w_attn,
                                                 const float* __restrict__ w_out,
                                                 const float* __restrict__ w_fc1,
                                                 const float* __restrict__ w_fc2,
                                                 __half* __restrict__ wq,
                                                 __half* __restrict__ wu,
                                                 __half* __restrict__ w1,
                                                 __half* __restrict__ w2)
{
    int t = blockIdx.x;
    const float* src; __half* dst;
    int row0, K, N, Nallot, ktiles;
    if      (t < 64)  { src=w_val;  dst=wq; row0=0;   K=256;  N=256;  Nallot=256;  ktiles=8;  t -= 0; }
    else if (t < 168) { src=w_off;  dst=wq; row0=256; K=256;  N=400;  Nallot=400;  ktiles=8;  t -= 64; }
    else if (t < 232) { src=w_attn; dst=wq; row0=656; K=256;  N=200;  Nallot=240;  ktiles=8;  t -= 168; }
    else if (t < 296) { src=w_out;  dst=wu; row0=0;   K=256;  N=256;  Nallot=256;  ktiles=8;  t -= 232; }
    else if (t < 552) { src=w_fc1;  dst=w1; row0=0;   K=256;  N=1024; Nallot=1024; ktiles=8;  t -= 296; }
    else              { src=w_fc2;  dst=w2; row0=0;   K=1024; N=256;  Nallot=256;  ktiles=32; t -= 552; }
    int kt = t % ktiles, nt = t / ktiles;
    int k0 = kt * 32, n0 = nt * 32;

    __shared__ float s[32][33];
    int tx = threadIdx.x & 31, ty = threadIdx.x >> 5;
#pragma unroll
    for (int j = ty; j < 32; j += 8) {
        int n = n0 + tx;
        s[j][tx] = (n < N) ? src[(size_t)(k0 + j) * N + n] : 0.0f;
    }
    __syncthreads();
#pragma unroll
    for (int j = ty; j < 32; j += 8) {
        int n = n0 + j;
        if (n < Nallot)
            dst[(size_t)(row0 + n) * K + k0 + tx] = __float2half(s[tx][j]);
    }
}

// ================= LayerNorm ==========================
__global__ void __launch_bounds__(256) ln_kernel(const float* __restrict__ x,
                                                 const float* __restrict__ gam,
                                                 const float* __restrict__ bet,
                                                 __half* __restrict__ o)
{
    int warp = threadIdx.x >> 5, lane = threadIdx.x & 31;
    int token = blockIdx.x * 8 + warp;
    const float4* x4 = reinterpret_cast<const float4*>(x) + (size_t)token * 64;
    float4 v0 = x4[lane * 2];
    float4 v1 = x4[lane * 2 + 1];
    float s  = v0.x + v0.y + v0.z + v0.w + v1.x + v1.y + v1.z + v1.w;
    float sq = v0.x*v0.x + v0.y*v0.y + v0.z*v0.z + v0.w*v0.w
             + v1.x*v1.x + v1.y*v1.y + v1.z*v1.z + v1.w*v1.w;
#pragma unroll
    for (int of = 16; of > 0; of >>= 1) {
        s  += __shfl_xor_sync(0xffffffffu, s,  of);
        sq += __shfl_xor_sync(0xffffffffu, sq, of);
    }
    float mean = s * (1.0f / CDIM);
    float var  = sq * (1.0f / CDIM) - mean * mean;
    float rstd = rsqrtf(var + 1e-5f);
    const float4* g4 = reinterpret_cast<const float4*>(gam);
    const float4* b4 = reinterpret_cast<const float4*>(bet);
    float r[8];
    {
        float4 ga = g4[lane * 2],     ba = b4[lane * 2];
        float4 gb = g4[lane * 2 + 1], bb = b4[lane * 2 + 1];
        r[0] = (v0.x - mean) * rstd * ga.x + ba.x;
        r[1] = (v0.y - mean) * rstd * ga.y + ba.y;
        r[2] = (v0.z - mean) * rstd * ga.z + ba.z;
        r[3] = (v0.w - mean) * rstd * ga.w + ba.w;
        r[4] = (v1.x - mean) * rstd * gb.x + bb.x;
        r[5] = (v1.y - mean) * rstd * gb.y + bb.y;
        r[6] = (v1.z - mean) * rstd * gb.z + bb.z;
        r[7] = (v1.w - mean) * rstd * gb.w + bb.w;
    }
    size_t base = (size_t)token * CDIM + lane * 8;
#pragma unroll
    for (int i = 0; i < 8; i += 2)
        *reinterpret_cast<__half2*>(o + base + i) =
            __floats2half2_rn(r[i], r[i + 1]);
}

// ================= warp-MMA GEMM (BM=128, BN=128, BK=64, 2-stage) ===========
enum { EP_QKV = 0, EP_RESID = 2, EP_GELU = 3 };

__device__ __forceinline__ float gelu_exact(float v) {
    return 0.5f * v * (1.0f + erff(v * 0.70710678118654752f));
}

#define STAGE_BYTES 32768
#define B_OFF       16384

template <int EPI>
__global__ void __launch_bounds__(256) mm_mma(const __half* __restrict__ A,
                                              const __half* __restrict__ B,
                                              const float* __restrict__ bias,
                                              float* __restrict__ Cout,
                                              const float* __restrict__ Res,
                                              __half* __restrict__ OutH,
                                              const float* __restrict__ b_off,
                                              const float* __restrict__ b_attn,
                                              float* __restrict__ OA,
                                              int K, int Nvalid, int ldc)
{
    extern __shared__ __align__(128) char smem[];
    const uint32_t sb = smem_u32(smem);
    const int tid = threadIdx.x;
    const int wid = tid >> 5, l = tid & 31;
    const int wm = wid & 3, wn = wid >> 2;
    const int m0 = blockIdx.y * 128, n0 = blockIdx.x * 128;

    float acc[2][8][4];
#pragma unroll
    for (int i = 0; i < 2; i++)
#pragma unroll
        for (int j = 0; j < 8; j++)
#pragma unroll
            for (int q = 0; q < 4; q++) acc[i][j][q] = 0.0f;

    const int KC = K >> 6;

    auto load_stage = [&](int kcidx) {
        int k0 = kcidx << 6;
        uint32_t st = sb + (kcidx & 1) * STAGE_BYTES;
#pragma unroll
        for (int i = 0; i < 4; i++) {
            int id = tid + i * 256;
            int r = id >> 3, c = id & 7;
            cp16(st + r * 128 + ((c ^ (r & 7)) << 4),
                 A + (size_t)(m0 + r) * K + k0 + c * 8);
        }
#pragma unroll
        for (int i = 0; i < 4; i++) {
            int id = tid + i * 256;
            int r = id >> 3, c = id & 7;
            cp16(st + B_OFF + r * 128 + ((c ^ (r & 7)) << 4),
                 B + (size_t)(n0 + r) * K + k0 + c * 8);
        }
        CP_COMMIT();
    };

    load_stage(0);

    const int rowA = wm * 32 + (l & 15);
    const int cxA  = l >> 4;
    const int rowB = wn * 64 + (l & 7) + ((l >> 4) << 3);
    const int cxB  = (l >> 3) & 1;

    for (int kc = 0; kc < KC; kc++) {
        if (kc + 1 < KC) {
            load_stage(kc + 1);
            CP_WAIT(1);
        } else {
            CP_WAIT(0);
        }
        __syncthreads();

        uint32_t ab = sb + (kc & 1) * STAGE_BYTES;
        uint32_t bb = ab + B_OFF;
#pragma unroll
        for (int ks = 0; ks < 4; ks++) {
            uint32_t a[2][4], b[4][4];
#pragma unroll
            for (int mt = 0; mt < 2; mt++) {
                int row = rowA + mt * 16;
                ldm4(a[mt], ab + row * 128 + (((ks * 2 + cxA) ^ (row & 7)) << 4));
            }
#pragma unroll
            for (int ntp = 0; ntp < 4; ntp++) {
                int row = rowB + ntp * 16;
                ldm4(b[ntp], bb + row * 128 + (((ks * 2 + cxB) ^ (row & 7)) << 4));
            }
#pragma unroll
            for (int mt = 0; mt < 2; mt++)
#pragma unroll
                for (int nt = 0; nt < 8; nt++)
                    mma_f16(acc[mt][nt], a[mt], &b[nt >> 1][(nt & 1) * 2]);
        }
        __syncthreads();
    }

    // ---- epilogue ----
#pragma unroll
    for (int mt = 0; mt < 2; mt++) {
#pragma unroll
        for (int nt = 0; nt < 8; nt++) {
            int col = n0 + wn * 64 + nt * 8 + (l & 3) * 2;
            if (col >= Nvalid) continue;
#pragma unroll
            for (int half = 0; half < 2; half++) {
                int row = m0 + wm * 32 + mt * 16 + (l >> 2) + half * 8;
                float v0 = acc[mt][nt][half * 2];
                float v1 = acc[mt][nt][half * 2 + 1];
                if (EPI == EP_QKV) {
                    if (col < 256) {
                        float2 bv = *reinterpret_cast<const float2*>(bias + col);
                        v0 += bv.x; v1 += bv.y;
                        int n = row / LQ, li = row - n * LQ;
                        int h = col >> 5, d = col & 31;
                        *reinterpret_cast<__half2*>(OutH +
                            ((size_t)((n * NHEADS + h) * LQ + li)) * DH + d) =
                            __floats2half2_rn(v0, v1);
                    } else if (col < 656) {
                        float2 bv = *reinterpret_cast<const float2*>(b_off + (col - 256));
                        v0 += bv.x; v1 += bv.y;
                        *reinterpret_cast<float2*>(OA + (size_t)row * OA_LD + (col - 256)) =
                            make_float2(v0, v1);
                    } else {
                        float2 bv = *reinterpret_cast<const float2*>(b_attn + (col - 656));
                        v0 += bv.x; v1 += bv.y;
                        *reinterpret_cast<float2*>(OA + (size_t)row * OA_LD + 400 + (col - 656)) =
                            make_float2(v0, v1);
                    }
                } else {
                    float2 bv = *reinterpret_cast<const float2*>(bias + col);
                    v0 += bv.x; v1 += bv.y;
                    if (EPI == EP_RESID) {
                        float2 r = *reinterpret_cast<const float2*>(Res + (size_t)row * ldc + col);
                        v0 += r.x; v1 += r.y;
                        *reinterpret_cast<float2*>(Cout + (size_t)row * ldc + col) =
                            make_float2(v0, v1);
                    }
                    if (EPI == EP_GELU) {
                        v0 = gelu_exact(v0);
                        v1 = gelu_exact(v1);
                        *reinterpret_cast<__half2*>(OutH + (size_t)row * ldc + col) =
                            __floats2half2_rn(v0, v1);
                    }
                }
            }
        }
    }
}

// ======== sampling v4: tap-dedup 5x5 patch via smem weight scatter ==========
// warp = (token, 4 heads); 8 lanes/head (hl); lane channels hl*4..hl*4+3.
__global__ void __launch_bounds__(256) sample_kernel(const float* __restrict__ refp)
{
    __shared__ float sw[8][4][25];      // [warp][head-in-warp][tap]

    int warpId = blockIdx.x * 8 + (threadIdx.x >> 5);   // < NLTOK*2
    int lane = threadIdx.x & 31;
    int wb = threadIdx.x >> 5;
    int token = warpId >> 1;
    int hq = lane >> 3;
    int hl = lane & 7;
    int h = (warpId & 1) * 4 + hq;
    int n = token / LQ;

    const float* oa = g_oa + (size_t)token * OA_LD;

    // softmax over 25 logits with 8 lanes: lane holds p = hl, hl+8, hl+16, (24)
    const float* lg = oa + 400 + h * NPTS;
    float l0 = __ldg(lg + hl);
    float l1 = __ldg(lg + hl + 8);
    float l2 = __ldg(lg + hl + 16);
    float l3 = (hl == 0) ? __ldg(lg + 24) : -1e30f;
    float mx = fmaxf(fmaxf(l0, l1), fmaxf(l2, l3));
#pragma unroll
    for (int o = 4; o > 0; o >>= 1)
        mx = fmaxf(mx, __shfl_xor_sync(0xffffffffu, mx, o, 8));
    float w0 = __expf(l0 - mx), w1 = __expf(l1 - mx), w2 = __expf(l2 - mx);
    float w3 = (hl == 0) ? __expf(l3 - mx) : 0.0f;
    float ssum = w0 + w1 + w2 + w3;
#pragma unroll
    for (int o = 4; o > 0; o >>= 1)
        ssum += __shfl_xor_sync(0xffffffffu, ssum, o, 8);
    float inv = 1.0f / ssum;
    w0 *= inv; w1 *= inv; w2 *= inv; w3 *= inv;

    float2 rp = __ldg(reinterpret_cast<const float2*>(refp) + token);
    float gxb = fmaf(rp.x, (float)WDIM, -0.5f);
    float gyb = fmaf(rp.y, (float)HDIM, -0.5f);

    const float2* offp = reinterpret_cast<const float2*>(oa + h * (NPTS * 2));
    const char* vbase = reinterpret_cast<const char*>(
        g_val + ((size_t)(n * NHEADS + h) * LQ) * DH) + hl * 8;

    // ---- pass 1: coord min/max over this head's 25 points ----
    int xmn = 1 << 20, xmx = -(1 << 20), ymn = 1 << 20, ymx = -(1 << 20);
#pragma unroll
    for (int s = 0; s < 3; s++) {
        float2 o2 = __ldg(offp + hl + s * 8);
        int x0 = (int)floorf(gxb + o2.x);
        int y0 = (int)floorf(gyb + o2.y);
        xmn = min(xmn, x0); xmx = max(xmx, x0);
        ymn = min(ymn, y0); ymx = max(ymx, y0);
    }
    if (hl == 0) {
        float2 o2 = __ldg(offp + 24);
        int x0 = (int)floorf(gxb + o2.x);
        int y0 = (int)floorf(gyb + o2.y);
        xmn = min(xmn, x0); xmx = max(xmx, x0);
        ymn = min(ymn, y0); ymx = max(ymx, y0);
    }
#pragma unroll
    for (int o = 4; o > 0; o >>= 1) {
        xmn = min(xmn, __shfl_xor_sync(0xffffffffu, xmn, o, 8));
        xmx = max(xmx, __shfl_xor_sync(0xffffffffu, xmx, o, 8));
        ymn = min(ymn, __shfl_xor_sync(0xffffffffu, ymn, o, 8));
        ymx = max(ymx, __shfl_xor_sync(0xffffffffu, ymx, o, 8));
    }
    bool fit = (xmx - xmn <= 3) && (ymx - ymn <= 3);

    float2 accA = make_float2(0.f, 0.f);
    float2 accB = make_float2(0.f, 0.f);

    if (__all_sync(0xffffffffu, fit)) {
        float* swh = &sw[wb][hq][0];
        swh[hl] = 0.f; swh[hl + 8] = 0.f; swh[hl + 16] = 0.f;
        if (hl == 0) swh[24] = 0.f;
        __syncwarp();

        // ---- pass 2: scatter bilinear*softmax weights into the patch ----
        auto contrib = [&](int p, float aw) {
            float2 o2 = __ldg(offp + p);
            float gx = gxb + o2.x, gy = gyb + o2.y;
            float fx0 = floorf(gx), fy0 = floorf(gy);
            float fx = gx - fx0, fy = gy - fy0;
            int x0 = (int)fx0, y0 = (int)fy0;
            float t0 = (1.f - fy) * aw, t1 = fy * aw;
            float w00 = (1.f - fx) * t0, w10 = fx * t0;
            float w01 = (1.f - fx) * t1, w11 = fx * t1;
            bool xv0 = (x0 >= 0) && (x0 < WDIM);
            bool xv1 = (x0 + 1 >= 0) && (x0 + 1 < WDIM);
            bool yv0 = (y0 >= 0) && (y0 < HDIM);
            bool yv1 = (y0 + 1 >= 0) && (y0 + 1 < HDIM);
            w00 = (xv0 && yv0) ? w00 : 0.f;
            w10 = (xv1 && yv0) ? w10 : 0.f;
            w01 = (xv0 && yv1) ? w01 : 0.f;
            w11 = (xv1 && yv1) ? w11 : 0.f;
            int idx = (y0 - ymn) * 5 + (x0 - xmn);
            atomicAdd(swh + idx,     w00);
            atomicAdd(swh + idx + 1, w10);
            atomicAdd(swh + idx + 5, w01);
            atomicAdd(swh + idx + 6, w11);
        };
        contrib(hl, w0);
        contrib(hl + 8, w1);
        contrib(hl + 16, w2);
        if (hl == 0) contrib(24, w3);
        __syncwarp();

        // ---- pass 3: load each distinct tap once, blend ----
        int yoff[5], xoff[5];
#pragma unroll
        for (int i = 0; i < 5; i++) {
            yoff[i] = min(max(ymn + i, 0), HDIM - 1) * WDIM;
            xoff[i] = min(max(xmn + i, 0), WDIM - 1);
        }
#pragma unroll
        for (int ty = 0; ty < 5; ty++) {
            __half2 aH = __floats2half2_rn(0.f, 0.f);
            __half2 bH = __floats2half2_rn(0.f, 0.f);
#pragma unroll
            for (int tx = 0; tx < 5; tx++) {
                float w = swh[ty * 5 + tx];
                uint2 v = *reinterpret_cast<const uint2*>(
                    vbase + (size_t)(yoff[ty] + xoff[tx]) * (DH * 2));
                __half2 hw = __floats2half2_rn(w, w);
                aH = __hfma2(*reinterpret_cast<__half2*>(&v.x), hw, aH);
                bH = __hfma2(*reinterpret_cast<__half2*>(&v.y), hw, bH);
            }
            float2 fA = __half22float2(aH), fB = __half22float2(bH);
            accA.x += fA.x; accA.y += fA.y;
            accB.x += fB.x; accB.y += fB.y;
        }
    } else {
        // ---- fallback: R12 per-point loop ----
#pragma unroll
        for (int p = 0; p < NPTS; p++) {
            float2 o2 = __ldg(offp + p);
            float src = (p < 8) ? w0 : (p < 16) ? w1 : (p < 24) ? w2 : w3;
            float aw = __shfl_sync(0xffffffffu, src, p & 7, 8);
            float gx = gxb + o2.x;
            float gy = gyb + o2.y;
            float fx0 = floorf(gx), fy0 = floorf(gy);
            float fx = gx - fx0, fy = gy - fy0;
            int x0 = (int)fx0, y0 = (int)fy0;
            float t0 = (1.f - fy) * aw, t1 = fy * aw;
            float w00 = (1.f - fx) * t0, w10 = fx * t0;
            float w01 = (1.f - fx) * t1, w11 = fx * t1;
            bool xv0 = (x0 >= 0) && (x0 < WDIM);
            bool xv1 = (x0 + 1 >= 0) && (x0 + 1 < WDIM);
            bool yv0 = (y0 >= 0) && (y0 < HDIM);
            bool yv1 = (y0 + 1 >= 0) && (y0 + 1 < HDIM);
#pragma unroll
            for (int tp = 0; tp < 4; tp++) {
                int xi = x0 + (tp & 1), yi = y0 + (tp >> 1);
                bool valid = (tp & 1 ? xv1 : xv0) && (tp >> 1 ? yv1 : yv0);
                float w = (tp == 0) ? w00 : (tp == 1) ? w10 : (tp == 2) ? w01 : w11;
                if (valid) {
                    uint2 v = *reinterpret_cast<const uint2*>(
                        vbase + (size_t)(yi * WDIM + xi) * (DH * 2));
                    float2 fA = __half22float2(*reinterpret_cast<__half2*>(&v.x));
                    float2 fB = __half22float2(*reinterpret_cast<__half2*>(&v.y));
                    accA.x = fmaf(w, fA.x, accA.x);
                    accA.y = fmaf(w, fA.y, accA.y);
                    accB.x = fmaf(w, fB.x, accB.x);
                    accB.y = fmaf(w, fB.y, accB.y);
                }
            }
        }
    }

    __half2 oA = __floats2half2_rn(accA.x, accA.y);
    __half2 oB = __floats2half2_rn(accB.x, accB.y);
    uint2 ov;
    ov.x = *reinterpret_cast<uint32_t*>(&oA);
    ov.y = *reinterpret_cast<uint32_t*>(&oB);
    *reinterpret_cast<uint2*>(g_at + (size_t)token * CDIM + h * DH + hl * 4) = ov;
}

// ================= launch =================
extern "C" void kernel_launch(void* const* d_in, const int* in_sizes, int n_in,
                              void* d_out, int out_size)
{
    (void)in_sizes; (void)n_in; (void)out_size;
    const float* x      = (const float*)d_in[0];
    const float* refp   = (const float*)d_in[1];
    const float* ln1g   = (const float*)d_in[4];
    const float* ln1b   = (const float*)d_in[5];
    const float* w_off  = (const float*)d_in[6];
    const float* b_off  = (const float*)d_in[7];
    const float* w_attn = (const float*)d_in[8];
    const float* b_attn = (const float*)d_in[9];
    const float* w_val  = (const float*)d_in[10];
    const float* b_val  = (const float*)d_in[11];
    const float* w_out  = (const float*)d_in[12];
    const float* b_out  = (const float*)d_in[13];
    const float* ln2g   = (const float*)d_in[14];
    const float* ln2b   = (const float*)d_in[15];
    const float* w_fc1  = (const float*)d_in[16];
    const float* b_fc1  = (const float*)d_in[17];
    const float* w_fc2  = (const float*)d_in[18];
    const float* b_fc2  = (const float*)d_in[19];
    float* out = (float*)d_out;

    __half *q, *at, *q2, *h1, *wq, *wu, *w1, *w2, *pval;
    float *poa, *px1;
    cudaGetSymbolAddress((void**)&q,  g_q);   cudaGetSymbolAddress((void**)&at, g_at);
    cudaGetSymbolAddress((void**)&q2, g_q2);  cudaGetSymbolAddress((void**)&h1, g_h1);
    cudaGetSymbolAddress((void**)&wq, g_wq);  cudaGetSymbolAddress((void**)&wu, g_wu);
    cudaGetSymbolAddress((void**)&w1, g_w1);  cudaGetSymbolAddress((void**)&w2, g_w2);
    cudaGetSymbolAddress((void**)&pval, g_val);
    cudaGetSymbolAddress((void**)&poa,  g_oa);
    cudaGetSymbolAddress((void**)&px1,  g_x1);

    const int SM_TOT = 2 * STAGE_BYTES;   // 64KB
    cudaFuncSetAttribute(mm_mma<EP_QKV>,   cudaFuncAttributeMaxDynamicSharedMemorySize, SM_TOT);
    cudaFuncSetAttribute(mm_mma<EP_RESID>, cudaFuncAttributeMaxDynamicSharedMemorySize, SM_TOT);
    cudaFuncSetAttribute(mm_mma<EP_GELU>,  cudaFuncAttributeMaxDynamicSharedMemorySize, SM_TOT);

    dim3 blk(256);
    const int MT = NLTOK / 128;   // 144

    wprep_all<<<808, blk>>>(w_val, w_off, w_attn, w_out, w_fc1, w_fc2, wq, wu, w1, w2);
    ln_kernel<<<NLTOK / 8, blk>>>(x, ln1g, ln1b, q);
    mm_mma<EP_QKV><<<dim3(7, MT), blk, SM_TOT>>>(q, wq, b_val, nullptr, nullptr, pval,
                                                 b_off, b_attn, poa, 256, 856, 0);
    sample_kernel<<<(NLTOK * 2) / 8, blk>>>(refp);
    mm_mma<EP_RESID><<<dim3(2, MT), blk, SM_TOT>>>(at, wu, b_out, px1, x, nullptr,
                                                   nullptr, nullptr, nullptr, 256, 256, 256);
    ln_kernel<<<NLTOK / 8, blk>>>(px1, ln2g, ln2b, q2);
    mm_mma<EP_GELU><<<dim3(8, MT), blk, SM_TOT>>>(q2, w1, b_fc1, nullptr, nullptr, h1,
                                                  nullptr, nullptr, nullptr, 256, 1024, 1024);
    mm_mma<EP_RESID><<<dim3(2, MT), blk, SM_TOT>>>(h1, w2, b_fc2, out, px1, nullptr,
                                                   nullptr, nullptr, nullptr, 1024, 256, 256);
}

// round 16
// speedup vs baseline: 1.1676x; 1.0012x over previous
#include <cuda_runtime.h>
#include <cuda_fp16.h>
#include <cstdint>
#include <math.h>

// Problem constants
#define NBATCH 2
#define HDIM   96
#define WDIM   96
#define CDIM   256
#define NHEADS 8
#define NPTS   25
#define DH     32
#define HIDDIM 1024
#define LQ     (HDIM*WDIM)      // 9216
#define NLTOK  (NBATCH*LQ)      // 18432
#define NQKV   896
#define OA_LD  600              // combined off(400)+attn(200) row stride

// ================= scratch (device globals, no allocation) =================
__device__ __align__(16) __half g_q  [NLTOK*CDIM];
__device__ __align__(16) __half g_at [NLTOK*CDIM];
__device__ __align__(16) __half g_q2 [NLTOK*CDIM];
__device__ __align__(16) __half g_h1 [NLTOK*HIDDIM];
__device__ __align__(16) __half g_val[NLTOK*CDIM];      // value [n,h,l,d], fp16
__device__ __align__(16) float  g_oa [NLTOK*OA_LD];
__device__ __align__(16) float  g_x1 [NLTOK*CDIM];
__device__ __align__(16) __half g_wq [NQKV*256];
__device__ __align__(16) __half g_wu [256*256];
__device__ __align__(16) __half g_w1 [1024*256];
__device__ __align__(16) __half g_w2 [256*1024];

// ================= low-level helpers ==================
__device__ __forceinline__ uint32_t smem_u32(const void* p) {
    uint32_t a;
    asm("{ .reg .u64 t; cvta.to.shared.u64 t, %1; cvt.u32.u64 %0, t; }" : "=r"(a) : "l"(p));
    return a;
}
__device__ __forceinline__ void cp16(uint32_t s, const void* g) {
    asm volatile("cp.async.cg.shared.global [%0], [%1], 16;" :: "r"(s), "l"(g));
}
#define CP_COMMIT() asm volatile("cp.async.commit_group;" ::: "memory")
#define CP_WAIT(n)  asm volatile("cp.async.wait_group %0;" :: "n"(n) : "memory")

__device__ __forceinline__ void ldm4(uint32_t* r, uint32_t addr) {
    asm volatile("ldmatrix.sync.aligned.m8n8.x4.shared.b16 {%0,%1,%2,%3}, [%4];"
                 : "=r"(r[0]), "=r"(r[1]), "=r"(r[2]), "=r"(r[3]) : "r"(addr));
}
__device__ __forceinline__ void mma_f16(float* d, const uint32_t* a, const uint32_t* b) {
    asm volatile("mma.sync.aligned.m16n8k16.row.col.f32.f16.f16.f32 "
                 "{%0,%1,%2,%3}, {%4,%5,%6,%7}, {%8,%9}, {%0,%1,%2,%3};"
                 : "+f"(d[0]), "+f"(d[1]), "+f"(d[2]), "+f"(d[3])
                 : "r"(a[0]), "r"(a[1]), "r"(a[2]), "r"(a[3]), "r"(b[0]), "r"(b[1]));
}

// ========== single mega weight-prep ========
__global__ void __launch_bounds__(256) wprep_all(const float* __restrict__ w_val,
                                                 const float* __restrict__ w_off,
                                                 const float* __restrict__ w_attn,
                                                 const float* __restrict__ w_out,
                                                 const float* __restrict__ w_fc1,
                                                 const float* __restrict__ w_fc2,
                                                 __half* __restrict__ wq,
                                                 __half* __restrict__ wu,
                                                 __half* __restrict__ w1,
                                                 __half* __restrict__ w2)
{
    int t = blockIdx.x;
    const float* src; __half* dst;
    int row0, K, N, Nallot, ktiles;
    if      (t < 64)  { src=w_val;  dst=wq; row0=0;   K=256;  N=256;  Nallot=256;  ktiles=8;  t -= 0; }
    else if (t < 168) { src=w_off;  dst=wq; row0=256; K=256;  N=400;  Nallot=400;  ktiles=8;  t -= 64; }
    else if (t < 232) { src=w_attn; dst=wq; row0=656; K=256;  N=200;  Nallot=240;  ktiles=8;  t -= 168; }
    else if (t < 296) { src=w_out;  dst=wu; row0=0;   K=256;  N=256;  Nallot=256;  ktiles=8;  t -= 232; }
    else if (t < 552) { src=w_fc1;  dst=w1; row0=0;   K=256;  N=1024; Nallot=1024; ktiles=8;  t -= 296; }
    else              { src=w_fc2;  dst=w2; row0=0;   K=1024; N=256;  Nallot=256;  ktiles=32; t -= 552; }
    int kt = t % ktiles, nt = t / ktiles;
    int k0 = kt * 32, n0 = nt * 32;

    __shared__ float s[32][33];
    int tx = threadIdx.x & 31, ty = threadIdx.x >> 5;
#pragma unroll
    for (int j = ty; j < 32; j += 8) {
        int n = n0 + tx;
        s[j][tx] = (n < N) ? src[(size_t)(k0 + j) * N + n] : 0.0f;
    }
    __syncthreads();
#pragma unroll
    for (int j = ty; j < 32; j += 8) {
        int n = n0 + j;
        if (n < Nallot)
            dst[(size_t)(row0 + n) * K + k0 + tx] = __float2half(s[tx][j]);
    }
}

// ================= LayerNorm ==========================
__global__ void __launch_bounds__(256) ln_kernel(const float* __restrict__ x,
                                                 const float* __restrict__ gam,
                                                 const float* __restrict__ bet,
                                                 __half* __restrict__ o)
{
    int warp = threadIdx.x >> 5, lane = threadIdx.x & 31;
    int token = blockIdx.x * 8 + warp;
    const float4* x4 = reinterpret_cast<const float4*>(x) + (size_t)token * 64;
    float4 v0 = x4[lane * 2];
    float4 v1 = x4[lane * 2 + 1];
    float s  = v0.x + v0.y + v0.z + v0.w + v1.x + v1.y + v1.z + v1.w;
    float sq = v0.x*v0.x + v0.y*v0.y + v0.z*v0.z + v0.w*v0.w
             + v1.x*v1.x + v1.y*v1.y + v1.z*v1.z + v1.w*v1.w;
#pragma unroll
    for (int of = 16; of > 0; of >>= 1) {
        s  += __shfl_xor_sync(0xffffffffu, s,  of);
        sq += __shfl_xor_sync(0xffffffffu, sq, of);
    }
    float mean = s * (1.0f / CDIM);
    float var  = sq * (1.0f / CDIM) - mean * mean;
    float rstd = rsqrtf(var + 1e-5f);
    const float4* g4 = reinterpret_cast<const float4*>(gam);
    const float4* b4 = reinterpret_cast<const float4*>(bet);
    float r[8];
    {
        float4 ga = g4[lane * 2],     ba = b4[lane * 2];
        float4 gb = g4[lane * 2 + 1], bb = b4[lane * 2 + 1];
        r[0] = (v0.x - mean) * rstd * ga.x + ba.x;
        r[1] = (v0.y - mean) * rstd * ga.y + ba.y;
        r[2] = (v0.z - mean) * rstd * ga.z + ba.z;
        r[3] = (v0.w - mean) * rstd * ga.w + ba.w;
        r[4] = (v1.x - mean) * rstd * gb.x + bb.x;
        r[5] = (v1.y - mean) * rstd * gb.y + bb.y;
        r[6] = (v1.z - mean) * rstd * gb.z + bb.z;
        r[7] = (v1.w - mean) * rstd * gb.w + bb.w;
    }
    size_t base = (size_t)token * CDIM + lane * 8;
#pragma unroll
    for (int i = 0; i < 8; i += 2)
        *reinterpret_cast<__half2*>(o + base + i) =
            __floats2half2_rn(r[i], r[i + 1]);
}

// ================= warp-MMA GEMM (BM=128, BN=128, BK=64, 2-stage) ===========
enum { EP_QKV = 0, EP_RESID = 2, EP_GELU = 3 };

__device__ __forceinline__ float gelu_exact(float v) {
    return 0.5f * v * (1.0f + erff(v * 0.70710678118654752f));
}

#define STAGE_BYTES 32768
#define B_OFF       16384

template <int EPI>
__global__ void __launch_bounds__(256) mm_mma(const __half* __restrict__ A,
                                              const __half* __restrict__ B,
                                              const float* __restrict__ bias,
                                              float* __restrict__ Cout,
                                              const float* __restrict__ Res,
                                              __half* __restrict__ OutH,
                                              const float* __restrict__ b_off,
                                              const float* __restrict__ b_attn,
                                              float* __restrict__ OA,
                                              int K, int Nvalid, int ldc)
{
    extern __shared__ __align__(128) char smem[];
    const uint32_t sb = smem_u32(smem);
    const int tid = threadIdx.x;
    const int wid = tid >> 5, l = tid & 31;
    const int wm = wid & 3, wn = wid >> 2;
    const int m0 = blockIdx.y * 128, n0 = blockIdx.x * 128;

    float acc[2][8][4];
#pragma unroll
    for (int i = 0; i < 2; i++)
#pragma unroll
        for (int j = 0; j < 8; j++)
#pragma unroll
            for (int q = 0; q < 4; q++) acc[i][j][q] = 0.0f;

    const int KC = K >> 6;

    auto load_stage = [&](int kcidx) {
        int k0 = kcidx << 6;
        uint32_t st = sb + (kcidx & 1) * STAGE_BYTES;
#pragma unroll
        for (int i = 0; i < 4; i++) {
            int id = tid + i * 256;
            int r = id >> 3, c = id & 7;
            cp16(st + r * 128 + ((c ^ (r & 7)) << 4),
                 A + (size_t)(m0 + r) * K + k0 + c * 8);
        }
#pragma unroll
        for (int i = 0; i < 4; i++) {
            int id = tid + i * 256;
            int r = id >> 3, c = id & 7;
            cp16(st + B_OFF + r * 128 + ((c ^ (r & 7)) << 4),
                 B + (size_t)(n0 + r) * K + k0 + c * 8);
        }
        CP_COMMIT();
    };

    load_stage(0);

    const int rowA = wm * 32 + (l & 15);
    const int cxA  = l >> 4;
    const int rowB = wn * 64 + (l & 7) + ((l >> 4) << 3);
    const int cxB  = (l >> 3) & 1;

    for (int kc = 0; kc < KC; kc++) {
        if (kc + 1 < KC) {
            load_stage(kc + 1);
            CP_WAIT(1);
        } else {
            CP_WAIT(0);
        }
        __syncthreads();

        uint32_t ab = sb + (kc & 1) * STAGE_BYTES;
        uint32_t bb = ab + B_OFF;
#pragma unroll
        for (int ks = 0; ks < 4; ks++) {
            uint32_t a[2][4], b[4][4];
#pragma unroll
            for (int mt = 0; mt < 2; mt++) {
                int row = rowA + mt * 16;
                ldm4(a[mt], ab + row * 128 + (((ks * 2 + cxA) ^ (row & 7)) << 4));
            }
#pragma unroll
            for (int ntp = 0; ntp < 4; ntp++) {
                int row = rowB + ntp * 16;
                ldm4(b[ntp], bb + row * 128 + (((ks * 2 + cxB) ^ (row & 7)) << 4));
            }
#pragma unroll
            for (int mt = 0; mt < 2; mt++)
#pragma unroll
                for (int nt = 0; nt < 8; nt++)
                    mma_f16(acc[mt][nt], a[mt], &b[nt >> 1][(nt & 1) * 2]);
        }
        __syncthreads();
    }

    // ---- epilogue ----
#pragma unroll
    for (int mt = 0; mt < 2; mt++) {
#pragma unroll
        for (int nt = 0; nt < 8; nt++) {
            int col = n0 + wn * 64 + nt * 8 + (l & 3) * 2;
            if (col >= Nvalid) continue;
#pragma unroll
            for (int half = 0; half < 2; half++) {
                int row = m0 + wm * 32 + mt * 16 + (l >> 2) + half * 8;
                float v0 = acc[mt][nt][half * 2];
                float v1 = acc[mt][nt][half * 2 + 1];
                if (EPI == EP_QKV) {
                    if (col < 256) {
                        float2 bv = *reinterpret_cast<const float2*>(bias + col);
                        v0 += bv.x; v1 += bv.y;
                        int n = row / LQ, li = row - n * LQ;
                        int h = col >> 5, d = col & 31;
                        *reinterpret_cast<__half2*>(OutH +
                            ((size_t)((n * NHEADS + h) * LQ + li)) * DH + d) =
                            __floats2half2_rn(v0, v1);
                    } else if (col < 656) {
                        float2 bv = *reinterpret_cast<const float2*>(b_off + (col - 256));
                        v0 += bv.x; v1 += bv.y;
                        *reinterpret_cast<float2*>(OA + (size_t)row * OA_LD + (col - 256)) =
                            make_float2(v0, v1);
                    } else {
                        float2 bv = *reinterpret_cast<const float2*>(b_attn + (col - 656));
                        v0 += bv.x; v1 += bv.y;
                        *reinterpret_cast<float2*>(OA + (size_t)row * OA_LD + 400 + (col - 656)) =
                            make_float2(v0, v1);
                    }
                } else {
                    float2 bv = *reinterpret_cast<const float2*>(bias + col);
                    v0 += bv.x; v1 += bv.y;
                    if (EPI == EP_RESID) {
                        float2 r = *reinterpret_cast<const float2*>(Res + (size_t)row * ldc + col);
                        v0 += r.x; v1 += r.y;
                        *reinterpret_cast<float2*>(Cout + (size_t)row * ldc + col) =
                            make_float2(v0, v1);
                    }
                    if (EPI == EP_GELU) {
                        v0 = gelu_exact(v0);
                        v1 = gelu_exact(v1);
                        *reinterpret_cast<__half2*>(OutH + (size_t)row * ldc + col) =
                            __floats2half2_rn(v0, v1);
                    }
                }
            }
        }
    }
}

// ======== sampling v5: tap-dedup, span-adaptive patch loop ==================
// warp = (token, 4 heads); 8 lanes/head (hl); lane channels hl*4..hl*4+3.
__global__ void __launch_bounds__(256) sample_kernel(const float* __restrict__ refp)
{
    __shared__ float sw[8][4][25];      // [warp][head-in-warp][tap], 5-stride

    int warpId = blockIdx.x * 8 + (threadIdx.x >> 5);   // < NLTOK*2
    int lane = threadIdx.x & 31;
    int wb = threadIdx.x >> 5;
    int token = warpId >> 1;
    int hq = lane >> 3;
    int hl = lane & 7;
    int h = (warpId & 1) * 4 + hq;
    int n = token / LQ;

    const float* oa = g_oa + (size_t)token * OA_LD;

    // softmax over 25 logits with 8 lanes: lane holds p = hl, hl+8, hl+16, (24)
    const float* lg = oa + 400 + h * NPTS;
    float l0 = __ldg(lg + hl);
    float l1 = __ldg(lg + hl + 8);
    float l2 = __ldg(lg + hl + 16);
    float l3 = (hl == 0) ? __ldg(lg + 24) : -1e30f;
    float mx = fmaxf(fmaxf(l0, l1), fmaxf(l2, l3));
#pragma unroll
    for (int o = 4; o > 0; o >>= 1)
        mx = fmaxf(mx, __shfl_xor_sync(0xffffffffu, mx, o, 8));
    float w0 = __expf(l0 - mx), w1 = __expf(l1 - mx), w2 = __expf(l2 - mx);
    float w3 = (hl == 0) ? __expf(l3 - mx) : 0.0f;
    float ssum = w0 + w1 + w2 + w3;
#pragma unroll
    for (int o = 4; o > 0; o >>= 1)
        ssum += __shfl_xor_sync(0xffffffffu, ssum, o, 8);
    float inv = 1.0f / ssum;
    w0 *= inv; w1 *= inv; w2 *= inv; w3 *= inv;

    float2 rp = __ldg(reinterpret_cast<const float2*>(refp) + token);
    float gxb = fmaf(rp.x, (float)WDIM, -0.5f);
    float gyb = fmaf(rp.y, (float)HDIM, -0.5f);

    const float2* offp = reinterpret_cast<const float2*>(oa + h * (NPTS * 2));
    const char* vbase = reinterpret_cast<const char*>(
        g_val + ((size_t)(n * NHEADS + h) * LQ) * DH) + hl * 8;

    // ---- pass 1: coord min/max over this head's 25 points ----
    int xmn = 1 << 20, xmx = -(1 << 20), ymn = 1 << 20, ymx = -(1 << 20);
#pragma unroll
    for (int s = 0; s < 3; s++) {
        float2 o2 = __ldg(offp + hl + s * 8);
        int x0 = (int)floorf(gxb + o2.x);
        int y0 = (int)floorf(gyb + o2.y);
        xmn = min(xmn, x0); xmx = max(xmx, x0);
        ymn = min(ymn, y0); ymx = max(ymx, y0);
    }
    if (hl == 0) {
        float2 o2 = __ldg(offp + 24);
        int x0 = (int)floorf(gxb + o2.x);
        int y0 = (int)floorf(gyb + o2.y);
        xmn = min(xmn, x0); xmx = max(xmx, x0);
        ymn = min(ymn, y0); ymx = max(ymx, y0);
    }
#pragma unroll
    for (int o = 4; o > 0; o >>= 1) {
        xmn = min(xmn, __shfl_xor_sync(0xffffffffu, xmn, o, 8));
        xmx = max(xmx, __shfl_xor_sync(0xffffffffu, xmx, o, 8));
        ymn = min(ymn, __shfl_xor_sync(0xffffffffu, ymn, o, 8));
        ymx = max(ymx, __shfl_xor_sync(0xffffffffu, ymx, o, 8));
    }
    bool fit = (xmx - xmn <= 3) && (ymx - ymn <= 3);

    float2 accA = make_float2(0.f, 0.f);
    float2 accB = make_float2(0.f, 0.f);

    if (__all_sync(0xffffffffu, fit)) {
        float* swh = &sw[wb][hq][0];
        swh[hl] = 0.f; swh[hl + 8] = 0.f; swh[hl + 16] = 0.f;
        if (hl == 0) swh[24] = 0.f;
        __syncwarp();

        // ---- pass 2: scatter bilinear*softmax weights into the patch ----
        auto contrib = [&](int p, float aw) {
            float2 o2 = __ldg(offp + p);
            float gx = gxb + o2.x, gy = gyb + o2.y;
            float fx0 = floorf(gx), fy0 = floorf(gy);
            float fx = gx - fx0, fy = gy - fy0;
            int x0 = (int)fx0, y0 = (int)fy0;
            float t0 = (1.f - fy) * aw, t1 = fy * aw;
            float w00 = (1.f - fx) * t0, w10 = fx * t0;
            float w01 = (1.f - fx) * t1, w11 = fx * t1;
            bool xv0 = (x0 >= 0) && (x0 < WDIM);
            bool xv1 = (x0 + 1 >= 0) && (x0 + 1 < WDIM);
            bool yv0 = (y0 >= 0) && (y0 < HDIM);
            bool yv1 = (y0 + 1 >= 0) && (y0 + 1 < HDIM);
            w00 = (xv0 && yv0) ? w00 : 0.f;
            w10 = (xv1 && yv0) ? w10 : 0.f;
            w01 = (xv0 && yv1) ? w01 : 0.f;
            w11 = (xv1 && yv1) ? w11 : 0.f;
            int idx = (y0 - ymn) * 5 + (x0 - xmn);
            atomicAdd(swh + idx,     w00);
            atomicAdd(swh + idx + 1, w10);
            atomicAdd(swh + idx + 5, w01);
            atomicAdd(swh + idx + 6, w11);
        };
        contrib(hl, w0);
        contrib(hl + 8, w1);
        contrib(hl + 16, w2);
        if (hl == 0) contrib(24, w3);
        __syncwarp();

        // ---- pass 3: span-adaptive — load only occupied taps ----
        int wx = xmx - xmn + 2;     // tap columns actually occupied (<=5)
        int wy = ymx - ymn + 2;     // tap rows actually occupied (<=5)
        for (int ty = 0; ty < wy; ty++) {
            int yc = min(max(ymn + ty, 0), HDIM - 1) * WDIM;
            __half2 aH = __floats2half2_rn(0.f, 0.f);
            __half2 bH = __floats2half2_rn(0.f, 0.f);
            for (int tx = 0; tx < wx; tx++) {
                float w = swh[ty * 5 + tx];
                int xc = min(max(xmn + tx, 0), WDIM - 1);
                uint2 v = *reinterpret_cast<const uint2*>(
                    vbase + (size_t)(yc + xc) * (DH * 2));
                __half2 hw = __floats2half2_rn(w, w);
                aH = __hfma2(*reinterpret_cast<__half2*>(&v.x), hw, aH);
                bH = __hfma2(*reinterpret_cast<__half2*>(&v.y), hw, bH);
            }
            float2 fA = __half22float2(aH), fB = __half22float2(bH);
            accA.x += fA.x; accA.y += fA.y;
            accB.x += fB.x; accB.y += fB.y;
        }
    } else {
        // ---- fallback: per-point loop ----
#pragma unroll
        for (int p = 0; p < NPTS; p++) {
            float2 o2 = __ldg(offp + p);
            float src = (p < 8) ? w0 : (p < 16) ? w1 : (p < 24) ? w2 : w3;
            float aw = __shfl_sync(0xffffffffu, src, p & 7, 8);
            float gx = gxb + o2.x;
            float gy = gyb + o2.y;
            float fx0 = floorf(gx), fy0 = floorf(gy);
            float fx = gx - fx0, fy = gy - fy0;
            int x0 = (int)fx0, y0 = (int)fy0;
            float t0 = (1.f - fy) * aw, t1 = fy * aw;
            float w00 = (1.f - fx) * t0, w10 = fx * t0;
            float w01 = (1.f - fx) * t1, w11 = fx * t1;
            bool xv0 = (x0 >= 0) && (x0 < WDIM);
            bool xv1 = (x0 + 1 >= 0) && (x0 + 1 < WDIM);
            bool yv0 = (y0 >= 0) && (y0 < HDIM);
            bool yv1 = (y0 + 1 >= 0) && (y0 + 1 < HDIM);
#pragma unroll
            for (int tp = 0; tp < 4; tp++) {
                int xi = x0 + (tp & 1), yi = y0 + (tp >> 1);
                bool valid = (tp & 1 ? xv1 : xv0) && (tp >> 1 ? yv1 : yv0);
                float w = (tp == 0) ? w00 : (tp == 1) ? w10 : (tp == 2) ? w01 : w11;
                if (valid) {
                    uint2 v = *reinterpret_cast<const uint2*>(
                        vbase + (size_t)(yi * WDIM + xi) * (DH * 2));
                    float2 fA = __half22float2(*reinterpret_cast<__half2*>(&v.x));
                    float2 fB = __half22float2(*reinterpret_cast<__half2*>(&v.y));
                    accA.x = fmaf(w, fA.x, accA.x);
                    accA.y = fmaf(w, fA.y, accA.y);
                    accB.x = fmaf(w, fB.x, accB.x);
                    accB.y = fmaf(w, fB.y, accB.y);
                }
            }
        }
    }

    __half2 oA = __floats2half2_rn(accA.x, accA.y);
    __half2 oB = __floats2half2_rn(accB.x, accB.y);
    uint2 ov;
    ov.x = *reinterpret_cast<uint32_t*>(&oA);
    ov.y = *reinterpret_cast<uint32_t*>(&oB);
    *reinterpret_cast<uint2*>(g_at + (size_t)token * CDIM + h * DH + hl * 4) = ov;
}

// ================= launch =================
extern "C" void kernel_launch(void* const* d_in, const int* in_sizes, int n_in,
                              void* d_out, int out_size)
{
    (void)in_sizes; (void)n_in; (void)out_size;
    const float* x      = (const float*)d_in[0];
    const float* refp   = (const float*)d_in[1];
    const float* ln1g   = (const float*)d_in[4];
    const float* ln1b   = (const float*)d_in[5];
    const float* w_off  = (const float*)d_in[6];
    const float* b_off  = (const float*)d_in[7];
    const float* w_attn = (const float*)d_in[8];
    const float* b_attn = (const float*)d_in[9];
    const float* w_val  = (const float*)d_in[10];
    const float* b_val  = (const float*)d_in[11];
    const float* w_out  = (const float*)d_in[12];
    const float* b_out  = (const float*)d_in[13];
    const float* ln2g   = (const float*)d_in[14];
    const float* ln2b   = (const float*)d_in[15];
    const float* w_fc1  = (const float*)d_in[16];
    const float* b_fc1  = (const float*)d_in[17];
    const float* w_fc2  = (const float*)d_in[18];
    const float* b_fc2  = (const float*)d_in[19];
    float* out = (float*)d_out;

    __half *q, *at, *q2, *h1, *wq, *wu, *w1, *w2, *pval;
    float *poa, *px1;
    cudaGetSymbolAddress((void**)&q,  g_q);   cudaGetSymbolAddress((void**)&at, g_at);
    cudaGetSymbolAddress((void**)&q2, g_q2);  cudaGetSymbolAddress((void**)&h1, g_h1);
    cudaGetSymbolAddress((void**)&wq, g_wq);  cudaGetSymbolAddress((void**)&wu, g_wu);
    cudaGetSymbolAddress((void**)&w1, g_w1);  cudaGetSymbolAddress((void**)&w2, g_w2);
    cudaGetSymbolAddress((void**)&pval, g_val);
    cudaGetSymbolAddress((void**)&poa,  g_oa);
    cudaGetSymbolAddress((void**)&px1,  g_x1);

    const int SM_TOT = 2 * STAGE_BYTES;   // 64KB
    cudaFuncSetAttribute(mm_mma<EP_QKV>,   cudaFuncAttributeMaxDynamicSharedMemorySize, SM_TOT);
    cudaFuncSetAttribute(mm_mma<EP_RESID>, cudaFuncAttributeMaxDynamicSharedMemorySize, SM_TOT);
    cudaFuncSetAttribute(mm_mma<EP_GELU>,  cudaFuncAttributeMaxDynamicSharedMemorySize, SM_TOT);

    dim3 blk(256);
    const int MT = NLTOK / 128;   // 144

    wprep_all<<<808, blk>>>(w_val, w_off, w_attn, w_out, w_fc1, w_fc2, wq, wu, w1, w2);
    ln_kernel<<<NLTOK / 8, blk>>>(x, ln1g, ln1b, q);
    mm_mma<EP_QKV><<<dim3(7, MT), blk, SM_TOT>>>(q, wq, b_val, nullptr, nullptr, pval,
                                                 b_off, b_attn, poa, 256, 856, 0);
    sample_kernel<<<(NLTOK * 2) / 8, blk>>>(refp);
    mm_mma<EP_RESID><<<dim3(2, MT), blk, SM_TOT>>>(at, wu, b_out, px1, x, nullptr,
                                                   nullptr, nullptr, nullptr, 256, 256, 256);
    ln_kernel<<<NLTOK / 8, blk>>>(px1, ln2g, ln2b, q2);
    mm_mma<EP_GELU><<<dim3(8, MT), blk, SM_TOT>>>(q2, w1, b_fc1, nullptr, nullptr, h1,
                                                  nullptr, nullptr, nullptr, 256, 1024, 1024);
    mm_mma<EP_RESID><<<dim3(2, MT), blk, SM_TOT>>>(h1, w2, b_fc2, out, px1, nullptr,
                                                   nullptr, nullptr, nullptr, 1024, 256, 256);
}